// round 8
// baseline (speedup 1.0000x reference)
#include <cuda_runtime.h>
#include <cuda_bf16.h>
#include <math.h>
#include <stdint.h>

#define CC 192
#define NB1 4096
#define NB2 1024

// ---------------- scratch (device globals; no allocation) ----------------
__device__ float d_freq[48];
__device__ float g_xn[4 * NB1 * CC];
__device__ float g_nb[4 * NB1 * CC];
__device__ float g_sage[4 * NB1 * CC];
__device__ float g_pool[4 * NB2 * CC];
__device__ float g_gdn[4 * NB2 * CC];
__device__ float g_sage2[4 * NB2 * CC];
__device__ float g_pool2[4 * 256 * CC];
__device__ float g_sqn[4 * NB1];
__device__ int   g_idx[4 * NB1 * 9];
__device__ int   g_perm[4 * NB2];
__device__ float g_sv[4 * NB2];
__device__ float g_scores[4 * NB1];
__device__ float g_scal[2];
__device__ __nv_bfloat16 g_pa[4 * NB1 * CC];
__device__ __nv_bfloat16 g_pb[4 * NB1 * CC];
__device__ __nv_bfloat16 g_pc[4 * NB1 * CC];

// ---------------- helpers (compute_100-portable) ----------------
__device__ __forceinline__ uint32_t smem_u32(const void* p) {
    uint32_t a;
    asm("{ .reg .u64 t; cvta.to.shared.u64 t, %1; cvt.u32.u64 %0, t; }" : "=r"(a) : "l"(p));
    return a;
}
__device__ __forceinline__ void ldsm4(uint32_t* r, uint32_t addr) {
    asm volatile("ldmatrix.sync.aligned.m8n8.x4.shared.b16 {%0,%1,%2,%3}, [%4];"
                 : "=r"(r[0]), "=r"(r[1]), "=r"(r[2]), "=r"(r[3]) : "r"(addr));
}
__device__ __forceinline__ void mma16816(float* d, const uint32_t* a,
                                         uint32_t b0, uint32_t b1) {
    asm volatile("mma.sync.aligned.m16n8k16.row.col.f32.bf16.bf16.f32 "
                 "{%0,%1,%2,%3}, {%4,%5,%6,%7}, {%8,%9}, {%0,%1,%2,%3};"
                 : "+f"(d[0]), "+f"(d[1]), "+f"(d[2]), "+f"(d[3])
                 : "r"(a[0]), "r"(a[1]), "r"(a[2]), "r"(a[3]), "r"(b0), "r"(b1));
}

// ---------------- positional-encoding frequency table ----------------
__global__ void k_freq() {
    int j = threadIdx.x;
    if (j < 48) d_freq[j] = (float)(1.0 / pow(10000.0, (double)(2 * j) / 96.0));
}

// ---------------- add pos-enc, build node features + sq norms ----------------
__global__ void k_prep(const float* __restrict__ x, float* __restrict__ xn,
                       float* __restrict__ sqn) {
    int n = blockIdx.x, b = blockIdx.y, c = threadIdx.x;
    int y = n >> 6, xw = n & 63;
    float v = x[(((size_t)b * CC + c) * 64 + y) * 64 + xw];
    float f, arg;
    if (c < 96) { f = d_freq[c >> 1];        arg = (float)y  * f; }
    else        { f = d_freq[(c - 96) >> 1]; arg = (float)xw * f; }
    v += (c & 1) ? cosf(arg) : sinf(arg);
    xn[((size_t)b * NB1 + n) * CC + c] = v;
    __shared__ float red[192];
    red[c] = v * v;
    __syncthreads();
    if (c < 64) red[c] += red[c + 64] + red[c + 128];
    __syncthreads();
    if (c < 32) {
        float s = red[c] + red[c + 32];
        for (int o = 16; o; o >>= 1) s += __shfl_down_sync(0xffffffffu, s, o);
        if (c == 0) sqn[b * NB1 + n] = s;
    }
}

// ---------------- generic squared-norm ----------------
__global__ void k_sqn(const float* __restrict__ xn, float* __restrict__ sqn, int N) {
    int n = blockIdx.x, b = blockIdx.y, c = threadIdx.x;
    float v = xn[((size_t)b * N + n) * CC + c];
    __shared__ float red[192];
    red[c] = v * v;
    __syncthreads();
    if (c < 64) red[c] += red[c + 64] + red[c + 128];
    __syncthreads();
    if (c < 32) {
        float s = red[c] + red[c + 32];
        for (int o = 16; o; o >>= 1) s += __shfl_down_sync(0xffffffffu, s, o);
        if (c == 0) sqn[b * N + n] = s;
    }
}

// ---------------- 3-way bf16 split ----------------
__global__ void k_split3(const float* __restrict__ xn, __nv_bfloat16* __restrict__ pa,
                         __nv_bfloat16* __restrict__ pb, __nv_bfloat16* __restrict__ pc,
                         int N) {
    size_t i = (((size_t)blockIdx.y * N + blockIdx.x) * CC) + threadIdx.x;
    float v = xn[i];
    __nv_bfloat16 a = __float2bfloat16(v);
    float r1 = v - __bfloat162float(a);
    __nv_bfloat16 b = __float2bfloat16(r1);
    float r2 = r1 - __bfloat162float(b);
    pa[i] = a; pb[i] = b; pc[i] = __float2bfloat16(r2);
}

// ---------------- mma.sync kNN v4: 16 warps, triple-buffered B ----------------
#define A_STRIDE 400
#define A_PLANE  (128 * A_STRIDE)           // 51200
#define OFF_B    (3 * A_PLANE)              // 153600
#define BBUF     (64 * A_STRIDE)            // 25600 per buffer (x3)
#define OFF_SQ   (OFF_B + 3 * BBUF)         // 230400 (2 x 256B)
#define KNN_SMEM (OFF_SQ + 512)             // 230912

__device__ __forceinline__ void issue_b(uint32_t dstBase, const __nv_bfloat16* plane,
                                        int colBase, int tid) {
    const char* g = (const char*)(plane + (size_t)colBase * CC);
#pragma unroll
    for (int t = 0; t < 3; t++) {
        int i = tid + t * 512;
        int row = i / 24, j = i - row * 24;
        uint32_t d = dstBase + row * A_STRIDE + j * 16;
        asm volatile("cp.async.cg.shared.global [%0], [%1], 16;"
                     :: "r"(d), "l"(g + row * 384 + j * 16));
    }
    asm volatile("cp.async.commit_group;" ::: "memory");
}

// 16-warp version: each warp = 16-row strip x 32-col half; 2 B tiles, 4 MMAs/plane.
template<int NA>
__device__ __forceinline__ void gemm_group(float (*acc)[4], uint32_t aBase, uint32_t bBase) {
#pragma unroll
    for (int kk = 0; kk < 192; kk += 16) {
        uint32_t bq[2][4];
#pragma unroll
        for (int n2 = 0; n2 < 2; n2++)
            ldsm4(bq[n2], bBase + (n2 << 4) * A_STRIDE + kk * 2);
#pragma unroll
        for (int ap = 0; ap < NA; ap++) {
            uint32_t a[4];
            ldsm4(a, aBase + ap * A_PLANE + kk * 2);
#pragma unroll
            for (int n2 = 0; n2 < 2; n2++) {
                mma16816(acc[2 * n2],     a, bq[n2][0], bq[n2][1]);
                mma16816(acc[2 * n2 + 1], a, bq[n2][2], bq[n2][3]);
            }
        }
    }
}

__global__ void __launch_bounds__(512, 1)
k_knn_mma(const __nv_bfloat16* __restrict__ pa, const __nv_bfloat16* __restrict__ pb,
          const __nv_bfloat16* __restrict__ pc, const float* __restrict__ sqn,
          int* __restrict__ idxOut, int N) {
    extern __shared__ char sm[];
    const uint32_t smb = smem_u32(sm);
    const int tid = threadIdx.x, warp = tid >> 5, lane = tid & 31;
    const int colhalf = warp >> 3, wstrip = (warp & 7) << 4;
    const int b = blockIdx.y, rowBase = blockIdx.x << 7;
    const __nv_bfloat16* P[3] = { pa + (size_t)b * N * CC, pb + (size_t)b * N * CC,
                                  pc + (size_t)b * N * CC };
    const float* SQ = sqn + (size_t)b * N;
    float* sqs = (float*)(sm + OFF_SQ);

    // prologue: loads for steps 0 and 1 (plane = step%3, buffer = step%3)
    issue_b(smb + OFF_B, P[0], 0, tid);
    issue_b(smb + OFF_B + BBUF, P[1], 0, tid);

    // resident A: 3 planes, 400B row stride (ldmatrix conflict-free)
#pragma unroll 1
    for (int p = 0; p < 3; p++) {
        const uint4* gp = (const uint4*)(P[p] + (size_t)rowBase * CC);
        for (int i = tid; i < 128 * 24; i += 512) {
            int row = i / 24, j = i - row * 24;
            *(uint4*)(sm + p * A_PLANE + row * A_STRIDE + j * 16) = gp[i];
        }
    }

    const int r0 = wstrip + (lane >> 2);
    const uint32_t aBase = smb + (wstrip + (lane & 15)) * A_STRIDE + (((uint32_t)lane >> 4) << 4);
    const uint32_t bOff  = ((lane & 7) + ((lane >> 4) << 3)) * A_STRIDE + (((lane >> 3) & 1) << 4)
                         + ((colhalf * 2) << 4) * A_STRIDE;   // this warp's first B tile

    const float sr0 = SQ[rowBase + r0], sr1 = SQ[rowBase + r0 + 8];

    float hd0[9], hd1[9]; int hi0[9], hi1[9];
#pragma unroll
    for (int q = 0; q < 9; q++) {
        hd0[q] = 3.4e38f; hi0[q] = 0x7fffffff;
        hd1[q] = 3.4e38f; hi1[q] = 0x7fffffff;
    }

    float acc[4][4];
    const int nsub = N >> 6, steps = nsub * 3;
    int sub = 0, p = 0;

#pragma unroll 1
    for (int step = 0; step < steps; step++) {
        asm volatile("cp.async.wait_group 1;" ::: "memory");
        __syncthreads();
        {   // issue load for step+2 (buffer (step+2)%3, plane (step+2)%3)
            int s2 = step + 2;
            if (s2 < steps)
                issue_b(smb + OFF_B + (s2 % 3) * BBUF, P[s2 % 3], (s2 / 3) << 6, tid);
        }
        if (p == 0) {
            if (tid < 64) sqs[tid + (sub & 1) * 64] = SQ[(sub << 6) + tid];
#pragma unroll
            for (int n = 0; n < 4; n++)
#pragma unroll
                for (int j = 0; j < 4; j++) acc[n][j] = 0.f;
        }
        const uint32_t bBase = smb + OFF_B + (step % 3) * BBUF + bOff;
        if (p == 0)      gemm_group<3>(acc, aBase, bBase);
        else if (p == 1) gemm_group<2>(acc, aBase, bBase);
        else {
            gemm_group<1>(acc, aBase, bBase);
            // ---- selection over this warp's 32-col half of the subtile ----
            const float* sq = sqs + (sub & 1) * 64;
            const int colBase = sub << 6;
#pragma unroll 1
            for (int n = 0; n < 4; n++) {
#pragma unroll
                for (int j = 0; j < 2; j++) {
                    int col = colhalf * 32 + n * 8 + ((lane & 3) << 1) + j;
                    float sc = sq[col];
                    int gcol = colBase + col;
                    float dv0 = fmaf(-2.f, acc[n][j], sr0 + sc);
                    if (dv0 < hd0[8]) {
                        hd0[8] = dv0; hi0[8] = gcol;
#pragma unroll
                        for (int q = 8; q > 0; q--) {
                            if (hd0[q - 1] > dv0) {
                                float td = hd0[q-1]; hd0[q-1] = hd0[q]; hd0[q] = td;
                                int   ti = hi0[q-1]; hi0[q-1] = hi0[q]; hi0[q] = ti;
                            } else break;
                        }
                    }
                    float dv1 = fmaf(-2.f, acc[n][2 + j], sr1 + sc);
                    if (dv1 < hd1[8]) {
                        hd1[8] = dv1; hi1[8] = gcol;
#pragma unroll
                        for (int q = 8; q > 0; q--) {
                            if (hd1[q - 1] > dv1) {
                                float td = hd1[q-1]; hd1[q-1] = hd1[q]; hd1[q] = td;
                                int   ti = hi1[q-1]; hi1[q-1] = hi1[q]; hi1[q] = ti;
                            } else break;
                        }
                    }
                }
            }
        }
        if (++p == 3) { p = 0; ++sub; }
    }

    // ---- merge 8 partial lists per row (lexicographic on (d, idx)) ----
    __syncthreads();
    float* md = (float*)(sm + OFF_B);                 // [128][8][9] dists
    int*   mi = (int*)(sm + OFF_B + 36864);           // [128][8][9] idxs
    const int part = (lane & 3) | (colhalf << 2);
#pragma unroll
    for (int q = 0; q < 9; q++) {
        md[(r0 * 8 + part) * 9 + q] = hd0[q];
        mi[(r0 * 8 + part) * 9 + q] = hi0[q];
        md[((r0 + 8) * 8 + part) * 9 + q] = hd1[q];
        mi[((r0 + 8) * 8 + part) * 9 + q] = hi1[q];
    }
    __syncthreads();
    if (part == 0) {
#pragma unroll 1
        for (int rr = 0; rr < 2; rr++) {
            int row = r0 + rr * 8;
            int p8[8] = {0, 0, 0, 0, 0, 0, 0, 0};
            size_t ob = ((size_t)b * N + rowBase + row) * 9;
            for (int q = 0; q < 9; q++) {
                float bd_ = 3.5e38f; int bi = 0x7fffffff, bm = 0;
#pragma unroll
                for (int m = 0; m < 8; m++) {
                    if (p8[m] < 9) {
                        float dv = md[(row * 8 + m) * 9 + p8[m]];
                        int   iv = mi[(row * 8 + m) * 9 + p8[m]];
                        if (dv < bd_ || (dv == bd_ && iv < bi)) { bd_ = dv; bi = iv; bm = m; }
                    }
                }
                idxOut[ob + q] = bi;
                p8[bm]++;
            }
        }
    }
}

// ---------------- gather + mean over 9 neighbors ----------------
__global__ void k_gather(const float* __restrict__ xn, const int* __restrict__ idx,
                         float* __restrict__ out, int N) {
    __shared__ int sid[9];
    int n = blockIdx.x, b = blockIdx.y, c = threadIdx.x;
    if (c < 9) sid[c] = idx[((size_t)b * N + n) * 9 + c];
    __syncthreads();
    const float* X = xn + (size_t)b * N * CC;
    float s = 0.f;
#pragma unroll
    for (int k = 0; k < 9; k++) s += X[(size_t)sid[k] * CC + c];
    out[((size_t)b * N + n) * CC + c] = s / 9.0f;
}

// ---------------- unified SAGE / GDN GEMM ----------------
template<bool GDN>
__global__ void k_lin(const float* __restrict__ A1, const float* __restrict__ A2,
                      const float* __restrict__ W1, const float* __restrict__ W2,
                      const float* __restrict__ bias, float* __restrict__ out) {
    int rowBase = blockIdx.x << 6, oBase = blockIdx.y << 6;
    __shared__ __align__(16) float A1s[16][68], A2s[16][68], W1s[16][68], W2s[16][68];
    int tid = threadIdx.x, ty = tid >> 4, tx = tid & 15;
    int lr = tid >> 2, lk = (tid & 3) << 2;
    float acc[4][4] = {};
    for (int kk = 0; kk < 192; kk += 16) {
        float4 a1 = *(const float4*)(A1 + (size_t)(rowBase + lr) * CC + kk + lk);
        float4 w1 = *(const float4*)(W1 + (size_t)(oBase + lr) * CC + kk + lk);
        float4 a2, w2;
        if (!GDN) {
            a2 = *(const float4*)(A2 + (size_t)(rowBase + lr) * CC + kk + lk);
            w2 = *(const float4*)(W2 + (size_t)(oBase + lr) * CC + kk + lk);
        }
        __syncthreads();
        if (GDN) { a1.x *= a1.x; a1.y *= a1.y; a1.z *= a1.z; a1.w *= a1.w; }
        A1s[lk+0][lr]=a1.x; A1s[lk+1][lr]=a1.y; A1s[lk+2][lr]=a1.z; A1s[lk+3][lr]=a1.w;
        W1s[lk+0][lr]=w1.x; W1s[lk+1][lr]=w1.y; W1s[lk+2][lr]=w1.z; W1s[lk+3][lr]=w1.w;
        if (!GDN) {
            A2s[lk+0][lr]=a2.x; A2s[lk+1][lr]=a2.y; A2s[lk+2][lr]=a2.z; A2s[lk+3][lr]=a2.w;
            W2s[lk+0][lr]=w2.x; W2s[lk+1][lr]=w2.y; W2s[lk+2][lr]=w2.z; W2s[lk+3][lr]=w2.w;
        }
        __syncthreads();
#pragma unroll
        for (int k = 0; k < 16; k++) {
            float4 xa = *(const float4*)&A1s[k][ty << 2];
            float4 u  = *(const float4*)&W1s[k][tx << 2];
            acc[0][0]+=xa.x*u.x; acc[0][1]+=xa.x*u.y; acc[0][2]+=xa.x*u.z; acc[0][3]+=xa.x*u.w;
            acc[1][0]+=xa.y*u.x; acc[1][1]+=xa.y*u.y; acc[1][2]+=xa.y*u.z; acc[1][3]+=xa.y*u.w;
            acc[2][0]+=xa.z*u.x; acc[2][1]+=xa.z*u.y; acc[2][2]+=xa.z*u.z; acc[2][3]+=xa.z*u.w;
            acc[3][0]+=xa.w*u.x; acc[3][1]+=xa.w*u.y; acc[3][2]+=xa.w*u.z; acc[3][3]+=xa.w*u.w;
            if (!GDN) {
                float4 xb = *(const float4*)&A2s[k][ty << 2];
                float4 v  = *(const float4*)&W2s[k][tx << 2];
                acc[0][0]+=xb.x*v.x; acc[0][1]+=xb.x*v.y; acc[0][2]+=xb.x*v.z; acc[0][3]+=xb.x*v.w;
                acc[1][0]+=xb.y*v.x; acc[1][1]+=xb.y*v.y; acc[1][2]+=xb.y*v.z; acc[1][3]+=xb.y*v.w;
                acc[2][0]+=xb.z*v.x; acc[2][1]+=xb.z*v.y; acc[2][2]+=xb.z*v.z; acc[2][3]+=xb.z*v.w;
                acc[3][0]+=xb.w*v.x; acc[3][1]+=xb.w*v.y; acc[3][2]+=xb.w*v.z; acc[3][3]+=xb.w*v.w;
            }
        }
    }
#pragma unroll
    for (int i = 0; i < 4; i++)
#pragma unroll
        for (int j = 0; j < 4; j++) {
            int oc = oBase + (tx << 2) + j;
            size_t off = (size_t)(rowBase + (ty << 2) + i) * CC + oc;
            if (GDN) out[off] = A1[off] * rsqrtf(acc[i][j] + bias[oc]);
            else     out[off] = acc[i][j] + bias[oc];
        }
}

// ---------------- ||w|| ----------------
__global__ void k_wnorm(const float* __restrict__ w, float* __restrict__ outp) {
    int c = threadIdx.x;
    __shared__ float red[192];
    float v = w[c];
    red[c] = v * v;
    __syncthreads();
    if (c < 64) red[c] += red[c + 64] + red[c + 128];
    __syncthreads();
    if (c < 32) {
        float s = red[c] + red[c + 32];
        for (int o = 16; o; o >>= 1) s += __shfl_down_sync(0xffffffffu, s, o);
        if (c == 0) *outp = sqrtf(s);
    }
}

// ---------------- pooling scores ----------------
__global__ void k_scores(const float* __restrict__ xn, const float* __restrict__ w,
                         const float* __restrict__ nrm, float* __restrict__ s) {
    int gw = (blockIdx.x << 3) + (threadIdx.x >> 5);
    int lane = threadIdx.x & 31;
    const float* row = xn + (size_t)gw * CC;
    float acc = 0.f;
#pragma unroll
    for (int c = lane; c < CC; c += 32) acc += row[c] * w[c];
    for (int o = 16; o; o >>= 1) acc += __shfl_down_sync(0xffffffffu, acc, o);
    if (!lane) s[gw] = tanhf(acc / nrm[0]);
}

// ---------------- stable bitonic sort: (score desc, idx asc) ----------------
__global__ void k_sort(const float* __restrict__ s, int* __restrict__ perm,
                       float* __restrict__ sv, int N, int KEEP) {
    extern __shared__ unsigned long long key[];
    int b = blockIdx.x, tid = threadIdx.x, nt = blockDim.x;
    for (int i = tid; i < N; i += nt) {
        unsigned u = __float_as_uint(s[b * N + i]);
        u = (u & 0x80000000u) ? ~u : (u | 0x80000000u);
        u = ~u;
        key[i] = ((unsigned long long)u << 32) | (unsigned)i;
    }
    __syncthreads();
    for (int k2 = 2; k2 <= N; k2 <<= 1)
        for (int j = k2 >> 1; j > 0; j >>= 1) {
            for (int i = tid; i < N; i += nt) {
                int ixj = i ^ j;
                if (ixj > i) {
                    unsigned long long a = key[i], c = key[ixj];
                    bool up = ((i & k2) == 0);
                    if ((a > c) == up) { key[i] = c; key[ixj] = a; }
                }
            }
            __syncthreads();
        }
    for (int i = tid; i < KEEP; i += nt) {
        unsigned long long a = key[i];
        unsigned idx = (unsigned)(a & 0xffffffffu);
        unsigned u = ~(unsigned)(a >> 32);
        u = (u & 0x80000000u) ? (u & 0x7fffffffu) : ~u;
        perm[b * KEEP + i] = (int)idx;
        sv[b * KEEP + i] = __uint_as_float(u);
    }
}

// ---------------- gather kept nodes, gate by score ----------------
__global__ void k_gatherpool(const float* __restrict__ in, const int* __restrict__ perm,
                             const float* __restrict__ sv, float* __restrict__ out,
                             int N, int KEEP) {
    int i = blockIdx.x, b = blockIdx.y, c = threadIdx.x;
    int p = perm[b * KEEP + i];
    out[((size_t)b * KEEP + i) * CC + c] = in[((size_t)b * N + p) * CC + c] * sv[b * KEEP + i];
}

// ---------------- final NHWC->NCHW ----------------
__global__ void k_final(const float* __restrict__ in, float* __restrict__ out) {
    int n = blockIdx.x, b = blockIdx.y, c = threadIdx.x;
    out[(((size_t)b * CC + c) * 16 + (n >> 4)) * 16 + (n & 15)] =
        in[((size_t)b * 256 + n) * CC + c];
}

// ---------------- launch ----------------
extern "C" void kernel_launch(void* const* d_in, const int* in_sizes, int n_in,
                              void* d_out, int out_size) {
    const float* x     = (const float*)d_in[0];
    const float* W1l   = (const float*)d_in[1];
    const float* b1l   = (const float*)d_in[2];
    const float* W1r   = (const float*)d_in[3];
    const float* p1w   = (const float*)d_in[4];
    const float* gbeta = (const float*)d_in[5];
    const float* ggam  = (const float*)d_in[6];
    const float* W2l   = (const float*)d_in[7];
    const float* b2l   = (const float*)d_in[8];
    const float* W2r   = (const float*)d_in[9];
    const float* p2w   = (const float*)d_in[10];
    float* out = (float*)d_out;

    float *xn, *nb, *sg, *pl, *gd, *sg2, *pl2, *sqn, *sv, *sc, *scal;
    int *idx, *perm;
    __nv_bfloat16 *pa, *pb, *pc;
    cudaGetSymbolAddress((void**)&xn,   g_xn);
    cudaGetSymbolAddress((void**)&nb,   g_nb);
    cudaGetSymbolAddress((void**)&sg,   g_sage);
    cudaGetSymbolAddress((void**)&pl,   g_pool);
    cudaGetSymbolAddress((void**)&gd,   g_gdn);
    cudaGetSymbolAddress((void**)&sg2,  g_sage2);
    cudaGetSymbolAddress((void**)&pl2,  g_pool2);
    cudaGetSymbolAddress((void**)&sqn,  g_sqn);
    cudaGetSymbolAddress((void**)&sv,   g_sv);
    cudaGetSymbolAddress((void**)&sc,   g_scores);
    cudaGetSymbolAddress((void**)&scal, g_scal);
    cudaGetSymbolAddress((void**)&idx,  g_idx);
    cudaGetSymbolAddress((void**)&perm, g_perm);
    cudaGetSymbolAddress((void**)&pa,   g_pa);
    cudaGetSymbolAddress((void**)&pb,   g_pb);
    cudaGetSymbolAddress((void**)&pc,   g_pc);

    cudaFuncSetAttribute(k_knn_mma, cudaFuncAttributeMaxDynamicSharedMemorySize, KNN_SMEM);

    k_freq<<<1, 64>>>();

    // ---- stage 1 (N = 4096) ----
    k_prep<<<dim3(NB1, 4), 192>>>(x, xn, sqn);
    k_split3<<<dim3(NB1, 4), 192>>>(xn, pa, pb, pc, NB1);
    k_knn_mma<<<dim3(NB1 / 128, 4), 512, KNN_SMEM>>>(pa, pb, pc, sqn, idx, NB1);
    k_gather<<<dim3(NB1, 4), 192>>>(xn, idx, nb, NB1);
    k_lin<false><<<dim3(4 * NB1 / 64, 3), 256>>>(nb, xn, W1l, W1r, b1l, sg);
    k_wnorm<<<1, 192>>>(p1w, scal);
    k_scores<<<4 * NB1 / 8, 256>>>(sg, p1w, scal, sc);
    k_sort<<<4, 1024, NB1 * 8>>>(sc, perm, sv, NB1, NB2);
    k_gatherpool<<<dim3(NB2, 4), 192>>>(sg, perm, sv, pl, NB1, NB2);
    k_lin<true><<<dim3(4 * NB2 / 64, 3), 256>>>(pl, pl, ggam, ggam, gbeta, gd);

    // ---- stage 2 (N = 1024) ----
    k_sqn<<<dim3(NB2, 4), 192>>>(gd, sqn, NB2);
    k_split3<<<dim3(NB2, 4), 192>>>(gd, pa, pb, pc, NB2);
    k_knn_mma<<<dim3(NB2 / 128, 4), 512, KNN_SMEM>>>(pa, pb, pc, sqn, idx, NB2);
    k_gather<<<dim3(NB2, 4), 192>>>(gd, idx, nb, NB2);
    k_lin<false><<<dim3(4 * NB2 / 64, 3), 256>>>(nb, gd, W2l, W2r, b2l, sg2);
    k_wnorm<<<1, 192>>>(p2w, scal + 1);
    k_scores<<<4 * NB2 / 8, 256>>>(sg2, p2w, scal + 1, sc);
    k_sort<<<4, 1024, NB2 * 8>>>(sc, perm, sv, NB2, 256);
    k_gatherpool<<<dim3(256, 4), 192>>>(sg2, perm, sv, pl2, NB2, 256);
    k_final<<<dim3(256, 4), 192>>>(pl2, out);
}

// round 9
// speedup vs baseline: 1.3250x; 1.3250x over previous
#include <cuda_runtime.h>
#include <cuda_fp16.h>
#include <math.h>
#include <stdint.h>

#define CC 192
#define NB1 4096
#define NB2 1024

// ---------------- scratch (device globals; no allocation) ----------------
__device__ float d_freq[48];
__device__ float g_xn[4 * NB1 * CC];
__device__ float g_nb[4 * NB1 * CC];
__device__ float g_sage[4 * NB1 * CC];
__device__ float g_pool[4 * NB2 * CC];
__device__ float g_gdn[4 * NB2 * CC];
__device__ float g_sage2[4 * NB2 * CC];
__device__ float g_pool2[4 * 256 * CC];
__device__ float g_sqn[4 * NB1];
__device__ int   g_idx[4 * NB1 * 9];
__device__ int   g_perm[4 * NB2];
__device__ float g_sv[4 * NB2];
__device__ float g_scores[4 * NB1];
__device__ float g_scal[2];
__device__ __half g_pa[4 * NB1 * CC];
__device__ __half g_pb[4 * NB1 * CC];

// ---------------- helpers (compute_100-portable) ----------------
__device__ __forceinline__ uint32_t smem_u32(const void* p) {
    uint32_t a;
    asm("{ .reg .u64 t; cvta.to.shared.u64 t, %1; cvt.u32.u64 %0, t; }" : "=r"(a) : "l"(p));
    return a;
}
__device__ __forceinline__ void ldsm4(uint32_t* r, uint32_t addr) {
    asm volatile("ldmatrix.sync.aligned.m8n8.x4.shared.b16 {%0,%1,%2,%3}, [%4];"
                 : "=r"(r[0]), "=r"(r[1]), "=r"(r[2]), "=r"(r[3]) : "r"(addr));
}
__device__ __forceinline__ void mma16816(float* d, const uint32_t* a,
                                         uint32_t b0, uint32_t b1) {
    asm volatile("mma.sync.aligned.m16n8k16.row.col.f32.f16.f16.f32 "
                 "{%0,%1,%2,%3}, {%4,%5,%6,%7}, {%8,%9}, {%0,%1,%2,%3};"
                 : "+f"(d[0]), "+f"(d[1]), "+f"(d[2]), "+f"(d[3])
                 : "r"(a[0]), "r"(a[1]), "r"(a[2]), "r"(a[3]), "r"(b0), "r"(b1));
}

// ---------------- positional-encoding frequency table ----------------
__global__ void k_freq() {
    int j = threadIdx.x;
    if (j < 48) d_freq[j] = (float)(1.0 / pow(10000.0, (double)(2 * j) / 96.0));
}

// ---------------- add pos-enc, build node features + sq norms ----------------
__global__ void k_prep(const float* __restrict__ x, float* __restrict__ xn,
                       float* __restrict__ sqn) {
    int n = blockIdx.x, b = blockIdx.y, c = threadIdx.x;
    int y = n >> 6, xw = n & 63;
    float v = x[(((size_t)b * CC + c) * 64 + y) * 64 + xw];
    float f, arg;
    if (c < 96) { f = d_freq[c >> 1];        arg = (float)y  * f; }
    else        { f = d_freq[(c - 96) >> 1]; arg = (float)xw * f; }
    v += (c & 1) ? cosf(arg) : sinf(arg);
    xn[((size_t)b * NB1 + n) * CC + c] = v;
    __shared__ float red[192];
    red[c] = v * v;
    __syncthreads();
    if (c < 64) red[c] += red[c + 64] + red[c + 128];
    __syncthreads();
    if (c < 32) {
        float s = red[c] + red[c + 32];
        for (int o = 16; o; o >>= 1) s += __shfl_down_sync(0xffffffffu, s, o);
        if (c == 0) sqn[b * NB1 + n] = s;
    }
}

// ---------------- generic squared-norm ----------------
__global__ void k_sqn(const float* __restrict__ xn, float* __restrict__ sqn, int N) {
    int n = blockIdx.x, b = blockIdx.y, c = threadIdx.x;
    float v = xn[((size_t)b * N + n) * CC + c];
    __shared__ float red[192];
    red[c] = v * v;
    __syncthreads();
    if (c < 64) red[c] += red[c + 64] + red[c + 128];
    __syncthreads();
    if (c < 32) {
        float s = red[c] + red[c + 32];
        for (int o = 16; o; o >>= 1) s += __shfl_down_sync(0xffffffffu, s, o);
        if (c == 0) sqn[b * N + n] = s;
    }
}

// ---------------- 2-way fp16 split ----------------
__global__ void k_split2(const float* __restrict__ xn, __half* __restrict__ pa,
                         __half* __restrict__ pb, int N) {
    size_t i = (((size_t)blockIdx.y * N + blockIdx.x) * CC) + threadIdx.x;
    float v = xn[i];
    __half a = __float2half_rn(v);
    float r = v - __half2float(a);
    pa[i] = a; pb[i] = __float2half_rn(r);
}

// ---------------- mma.sync kNN v5: fp16 x2 planes, triple-buffered B ----------------
#define A_STRIDE 400
#define A_PLANE  (128 * A_STRIDE)           // 51200
#define OFF_B    (2 * A_PLANE)              // 102400
#define BBUF     (64 * A_STRIDE)            // 25600 per buffer (x3)
#define OFF_SQ   (OFF_B + 3 * BBUF)         // 179200
#define KNN_SMEM (OFF_SQ + 512)             // 179712

__device__ __forceinline__ void issue_b(uint32_t dstBase, const __half* plane,
                                        int colBase, int tid) {
    const char* g = (const char*)(plane + (size_t)colBase * CC);
#pragma unroll
    for (int t = 0; t < 6; t++) {
        int i = tid + t * 256;
        int row = i / 24, j = i - row * 24;
        uint32_t d = dstBase + row * A_STRIDE + j * 16;
        asm volatile("cp.async.cg.shared.global [%0], [%1], 16;"
                     :: "r"(d), "l"(g + row * 384 + j * 16));
    }
    asm volatile("cp.async.commit_group;" ::: "memory");
}

// One B plane vs both A planes: per k-chunk load 4 B frags + 2 A frags, 16 MMAs.
__device__ __forceinline__ void gemm2(float (*acc)[4], uint32_t aBase, uint32_t bBase) {
#pragma unroll
    for (int kk = 0; kk < 192; kk += 16) {
        uint32_t bq[4][4];
#pragma unroll
        for (int n2 = 0; n2 < 4; n2++)
            ldsm4(bq[n2], bBase + (n2 << 4) * A_STRIDE + kk * 2);
#pragma unroll
        for (int ap = 0; ap < 2; ap++) {
            uint32_t a[4];
            ldsm4(a, aBase + ap * A_PLANE + kk * 2);
#pragma unroll
            for (int n2 = 0; n2 < 4; n2++) {
                mma16816(acc[2 * n2],     a, bq[n2][0], bq[n2][1]);
                mma16816(acc[2 * n2 + 1], a, bq[n2][2], bq[n2][3]);
            }
        }
    }
}

__global__ void __launch_bounds__(256, 1)
k_knn_mma(const __half* __restrict__ pa, const __half* __restrict__ pb,
          const float* __restrict__ sqn, int* __restrict__ idxOut, int N) {
    extern __shared__ char sm[];
    const uint32_t smb = smem_u32(sm);
    const int tid = threadIdx.x, warp = tid >> 5, lane = tid & 31;
    const int b = blockIdx.y, rowBase = blockIdx.x << 7;
    const __half* P[2] = { pa + (size_t)b * N * CC, pb + (size_t)b * N * CC };
    const float* SQ = sqn + (size_t)b * N;
    float* sqs = (float*)(sm + OFF_SQ);

    // prologue: loads for steps 0 (plane0) and 1 (plane1), buffers 0 and 1
    issue_b(smb + OFF_B, P[0], 0, tid);
    issue_b(smb + OFF_B + BBUF, P[1], 0, tid);

    // resident A: 2 planes, 400B row stride (ldmatrix conflict-free)
#pragma unroll 1
    for (int p = 0; p < 2; p++) {
        const uint4* gp = (const uint4*)(P[p] + (size_t)rowBase * CC);
        for (int i = tid; i < 128 * 24; i += 256) {
            int row = i / 24, j = i - row * 24;
            *(uint4*)(sm + p * A_PLANE + row * A_STRIDE + j * 16) = gp[i];
        }
    }

    const int strip = warp << 4;
    const int r0 = strip + (lane >> 2);
    const uint32_t aBase = smb + (strip + (lane & 15)) * A_STRIDE + (((uint32_t)lane >> 4) << 4);
    const uint32_t bOff  = ((lane & 7) + ((lane >> 4) << 3)) * A_STRIDE + (((lane >> 3) & 1) << 4);

    const float sr0 = SQ[rowBase + r0], sr1 = SQ[rowBase + r0 + 8];

    float hd0[9], hd1[9]; int hi0[9], hi1[9];
#pragma unroll
    for (int q = 0; q < 9; q++) {
        hd0[q] = 3.4e38f; hi0[q] = 0x7fffffff;
        hd1[q] = 3.4e38f; hi1[q] = 0x7fffffff;
    }

    float acc[8][4];
    const int nsub = N >> 6, steps = nsub * 2;

#pragma unroll 1
    for (int step = 0; step < steps; step++) {
        const int sub = step >> 1, p = step & 1;
        asm volatile("cp.async.wait_group 1;" ::: "memory");
        __syncthreads();
        {   // issue load for step+2 (buffer (step+2)%3, plane (step+2)&1)
            int s2 = step + 2;
            if (s2 < steps)
                issue_b(smb + OFF_B + (s2 % 3) * BBUF, P[s2 & 1], (s2 >> 1) << 6, tid);
        }
        if (p == 0) {
            if (tid < 64) sqs[(sub & 1) * 64 + tid] = SQ[(sub << 6) + tid];
#pragma unroll
            for (int n = 0; n < 8; n++)
#pragma unroll
                for (int j = 0; j < 4; j++) acc[n][j] = 0.f;
        }
        gemm2(acc, aBase, smb + OFF_B + (step % 3) * BBUF + bOff);
        if (p == 1) {
            // ---- selection over this 64-col subtile ----
            const float* sq = sqs + (sub & 1) * 64;
            const int colBase = sub << 6;
#pragma unroll 1
            for (int n = 0; n < 8; n++) {
#pragma unroll
                for (int j = 0; j < 2; j++) {
                    int col = (n << 3) + ((lane & 3) << 1) + j;
                    float sc = sq[col];
                    int gcol = colBase + col;
                    float dv0 = fmaf(-2.f, acc[n][j], sr0 + sc);
                    if (dv0 < hd0[8]) {
                        hd0[8] = dv0; hi0[8] = gcol;
#pragma unroll
                        for (int q = 8; q > 0; q--) {
                            if (hd0[q - 1] > dv0) {
                                float td = hd0[q-1]; hd0[q-1] = hd0[q]; hd0[q] = td;
                                int   ti = hi0[q-1]; hi0[q-1] = hi0[q]; hi0[q] = ti;
                            } else break;
                        }
                    }
                    float dv1 = fmaf(-2.f, acc[n][2 + j], sr1 + sc);
                    if (dv1 < hd1[8]) {
                        hd1[8] = dv1; hi1[8] = gcol;
#pragma unroll
                        for (int q = 8; q > 0; q--) {
                            if (hd1[q - 1] > dv1) {
                                float td = hd1[q-1]; hd1[q-1] = hd1[q]; hd1[q] = td;
                                int   ti = hi1[q-1]; hi1[q-1] = hi1[q]; hi1[q] = ti;
                            } else break;
                        }
                    }
                }
            }
        }
    }

    // ---- merge 4 partial lists per row (lexicographic on (d, idx)) ----
    __syncthreads();
    float* md = (float*)(sm + OFF_B);            // [128][4][9] dists
    int*   mi = (int*)(sm + OFF_B + 18432);      // [128][4][9] idxs
    const int part = lane & 3;
#pragma unroll
    for (int q = 0; q < 9; q++) {
        md[(r0 * 4 + part) * 9 + q] = hd0[q];
        mi[(r0 * 4 + part) * 9 + q] = hi0[q];
        md[((r0 + 8) * 4 + part) * 9 + q] = hd1[q];
        mi[((r0 + 8) * 4 + part) * 9 + q] = hi1[q];
    }
    __syncthreads();
    if (part == 0) {
#pragma unroll 1
        for (int rr = 0; rr < 2; rr++) {
            int row = r0 + rr * 8;
            int p4[4] = {0, 0, 0, 0};
            size_t ob = ((size_t)b * N + rowBase + row) * 9;
            for (int q = 0; q < 9; q++) {
                float bd_ = 3.5e38f; int bi = 0x7fffffff, bm = 0;
#pragma unroll
                for (int m = 0; m < 4; m++) {
                    if (p4[m] < 9) {
                        float dv = md[(row * 4 + m) * 9 + p4[m]];
                        int   iv = mi[(row * 4 + m) * 9 + p4[m]];
                        if (dv < bd_ || (dv == bd_ && iv < bi)) { bd_ = dv; bi = iv; bm = m; }
                    }
                }
                idxOut[ob + q] = bi;
                p4[bm]++;
            }
        }
    }
}

// ---------------- gather + mean over 9 neighbors ----------------
__global__ void k_gather(const float* __restrict__ xn, const int* __restrict__ idx,
                         float* __restrict__ out, int N) {
    __shared__ int sid[9];
    int n = blockIdx.x, b = blockIdx.y, c = threadIdx.x;
    if (c < 9) sid[c] = idx[((size_t)b * N + n) * 9 + c];
    __syncthreads();
    const float* X = xn + (size_t)b * N * CC;
    float s = 0.f;
#pragma unroll
    for (int k = 0; k < 9; k++) s += X[(size_t)sid[k] * CC + c];
    out[((size_t)b * N + n) * CC + c] = s / 9.0f;
}

// ---------------- unified SAGE / GDN GEMM ----------------
template<bool GDN>
__global__ void k_lin(const float* __restrict__ A1, const float* __restrict__ A2,
                      const float* __restrict__ W1, const float* __restrict__ W2,
                      const float* __restrict__ bias, float* __restrict__ out) {
    int rowBase = blockIdx.x << 6, oBase = blockIdx.y << 6;
    __shared__ __align__(16) float A1s[16][68], A2s[16][68], W1s[16][68], W2s[16][68];
    int tid = threadIdx.x, ty = tid >> 4, tx = tid & 15;
    int lr = tid >> 2, lk = (tid & 3) << 2;
    float acc[4][4] = {};
    for (int kk = 0; kk < 192; kk += 16) {
        float4 a1 = *(const float4*)(A1 + (size_t)(rowBase + lr) * CC + kk + lk);
        float4 w1 = *(const float4*)(W1 + (size_t)(oBase + lr) * CC + kk + lk);
        float4 a2, w2;
        if (!GDN) {
            a2 = *(const float4*)(A2 + (size_t)(rowBase + lr) * CC + kk + lk);
            w2 = *(const float4*)(W2 + (size_t)(oBase + lr) * CC + kk + lk);
        }
        __syncthreads();
        if (GDN) { a1.x *= a1.x; a1.y *= a1.y; a1.z *= a1.z; a1.w *= a1.w; }
        A1s[lk+0][lr]=a1.x; A1s[lk+1][lr]=a1.y; A1s[lk+2][lr]=a1.z; A1s[lk+3][lr]=a1.w;
        W1s[lk+0][lr]=w1.x; W1s[lk+1][lr]=w1.y; W1s[lk+2][lr]=w1.z; W1s[lk+3][lr]=w1.w;
        if (!GDN) {
            A2s[lk+0][lr]=a2.x; A2s[lk+1][lr]=a2.y; A2s[lk+2][lr]=a2.z; A2s[lk+3][lr]=a2.w;
            W2s[lk+0][lr]=w2.x; W2s[lk+1][lr]=w2.y; W2s[lk+2][lr]=w2.z; W2s[lk+3][lr]=w2.w;
        }
        __syncthreads();
#pragma unroll
        for (int k = 0; k < 16; k++) {
            float4 xa = *(const float4*)&A1s[k][ty << 2];
            float4 u  = *(const float4*)&W1s[k][tx << 2];
            acc[0][0]+=xa.x*u.x; acc[0][1]+=xa.x*u.y; acc[0][2]+=xa.x*u.z; acc[0][3]+=xa.x*u.w;
            acc[1][0]+=xa.y*u.x; acc[1][1]+=xa.y*u.y; acc[1][2]+=xa.y*u.z; acc[1][3]+=xa.y*u.w;
            acc[2][0]+=xa.z*u.x; acc[2][1]+=xa.z*u.y; acc[2][2]+=xa.z*u.z; acc[2][3]+=xa.z*u.w;
            acc[3][0]+=xa.w*u.x; acc[3][1]+=xa.w*u.y; acc[3][2]+=xa.w*u.z; acc[3][3]+=xa.w*u.w;
            if (!GDN) {
                float4 xb = *(const float4*)&A2s[k][ty << 2];
                float4 v  = *(const float4*)&W2s[k][tx << 2];
                acc[0][0]+=xb.x*v.x; acc[0][1]+=xb.x*v.y; acc[0][2]+=xb.x*v.z; acc[0][3]+=xb.x*v.w;
                acc[1][0]+=xb.y*v.x; acc[1][1]+=xb.y*v.y; acc[1][2]+=xb.y*v.z; acc[1][3]+=xb.y*v.w;
                acc[2][0]+=xb.z*v.x; acc[2][1]+=xb.z*v.y; acc[2][2]+=xb.z*v.z; acc[2][3]+=xb.z*v.w;
                acc[3][0]+=xb.w*v.x; acc[3][1]+=xb.w*v.y; acc[3][2]+=xb.w*v.z; acc[3][3]+=xb.w*v.w;
            }
        }
    }
#pragma unroll
    for (int i = 0; i < 4; i++)
#pragma unroll
        for (int j = 0; j < 4; j++) {
            int oc = oBase + (tx << 2) + j;
            size_t off = (size_t)(rowBase + (ty << 2) + i) * CC + oc;
            if (GDN) out[off] = A1[off] * rsqrtf(acc[i][j] + bias[oc]);
            else     out[off] = acc[i][j] + bias[oc];
        }
}

// ---------------- ||w|| ----------------
__global__ void k_wnorm(const float* __restrict__ w, float* __restrict__ outp) {
    int c = threadIdx.x;
    __shared__ float red[192];
    float v = w[c];
    red[c] = v * v;
    __syncthreads();
    if (c < 64) red[c] += red[c + 64] + red[c + 128];
    __syncthreads();
    if (c < 32) {
        float s = red[c] + red[c + 32];
        for (int o = 16; o; o >>= 1) s += __shfl_down_sync(0xffffffffu, s, o);
        if (c == 0) *outp = sqrtf(s);
    }
}

// ---------------- pooling scores ----------------
__global__ void k_scores(const float* __restrict__ xn, const float* __restrict__ w,
                         const float* __restrict__ nrm, float* __restrict__ s) {
    int gw = (blockIdx.x << 3) + (threadIdx.x >> 5);
    int lane = threadIdx.x & 31;
    const float* row = xn + (size_t)gw * CC;
    float acc = 0.f;
#pragma unroll
    for (int c = lane; c < CC; c += 32) acc += row[c] * w[c];
    for (int o = 16; o; o >>= 1) acc += __shfl_down_sync(0xffffffffu, acc, o);
    if (!lane) s[gw] = tanhf(acc / nrm[0]);
}

// ---------------- stable bitonic sort: (score desc, idx asc) ----------------
__global__ void k_sort(const float* __restrict__ s, int* __restrict__ perm,
                       float* __restrict__ sv, int N, int KEEP) {
    extern __shared__ unsigned long long key[];
    int b = blockIdx.x, tid = threadIdx.x, nt = blockDim.x;
    for (int i = tid; i < N; i += nt) {
        unsigned u = __float_as_uint(s[b * N + i]);
        u = (u & 0x80000000u) ? ~u : (u | 0x80000000u);
        u = ~u;
        key[i] = ((unsigned long long)u << 32) | (unsigned)i;
    }
    __syncthreads();
    for (int k2 = 2; k2 <= N; k2 <<= 1)
        for (int j = k2 >> 1; j > 0; j >>= 1) {
            for (int i = tid; i < N; i += nt) {
                int ixj = i ^ j;
                if (ixj > i) {
                    unsigned long long a = key[i], c = key[ixj];
                    bool up = ((i & k2) == 0);
                    if ((a > c) == up) { key[i] = c; key[ixj] = a; }
                }
            }
            __syncthreads();
        }
    for (int i = tid; i < KEEP; i += nt) {
        unsigned long long a = key[i];
        unsigned idx = (unsigned)(a & 0xffffffffu);
        unsigned u = ~(unsigned)(a >> 32);
        u = (u & 0x80000000u) ? (u & 0x7fffffffu) : ~u;
        perm[b * KEEP + i] = (int)idx;
        sv[b * KEEP + i] = __uint_as_float(u);
    }
}

// ---------------- gather kept nodes, gate by score ----------------
__global__ void k_gatherpool(const float* __restrict__ in, const int* __restrict__ perm,
                             const float* __restrict__ sv, float* __restrict__ out,
                             int N, int KEEP) {
    int i = blockIdx.x, b = blockIdx.y, c = threadIdx.x;
    int p = perm[b * KEEP + i];
    out[((size_t)b * KEEP + i) * CC + c] = in[((size_t)b * N + p) * CC + c] * sv[b * KEEP + i];
}

// ---------------- final NHWC->NCHW ----------------
__global__ void k_final(const float* __restrict__ in, float* __restrict__ out) {
    int n = blockIdx.x, b = blockIdx.y, c = threadIdx.x;
    out[(((size_t)b * CC + c) * 16 + (n >> 4)) * 16 + (n & 15)] =
        in[((size_t)b * 256 + n) * CC + c];
}

// ---------------- launch ----------------
extern "C" void kernel_launch(void* const* d_in, const int* in_sizes, int n_in,
                              void* d_out, int out_size) {
    const float* x     = (const float*)d_in[0];
    const float* W1l   = (const float*)d_in[1];
    const float* b1l   = (const float*)d_in[2];
    const float* W1r   = (const float*)d_in[3];
    const float* p1w   = (const float*)d_in[4];
    const float* gbeta = (const float*)d_in[5];
    const float* ggam  = (const float*)d_in[6];
    const float* W2l   = (const float*)d_in[7];
    const float* b2l   = (const float*)d_in[8];
    const float* W2r   = (const float*)d_in[9];
    const float* p2w   = (const float*)d_in[10];
    float* out = (float*)d_out;

    float *xn, *nb, *sg, *pl, *gd, *sg2, *pl2, *sqn, *sv, *sc, *scal;
    int *idx, *perm;
    __half *pa, *pb;
    cudaGetSymbolAddress((void**)&xn,   g_xn);
    cudaGetSymbolAddress((void**)&nb,   g_nb);
    cudaGetSymbolAddress((void**)&sg,   g_sage);
    cudaGetSymbolAddress((void**)&pl,   g_pool);
    cudaGetSymbolAddress((void**)&gd,   g_gdn);
    cudaGetSymbolAddress((void**)&sg2,  g_sage2);
    cudaGetSymbolAddress((void**)&pl2,  g_pool2);
    cudaGetSymbolAddress((void**)&sqn,  g_sqn);
    cudaGetSymbolAddress((void**)&sv,   g_sv);
    cudaGetSymbolAddress((void**)&sc,   g_scores);
    cudaGetSymbolAddress((void**)&scal, g_scal);
    cudaGetSymbolAddress((void**)&idx,  g_idx);
    cudaGetSymbolAddress((void**)&perm, g_perm);
    cudaGetSymbolAddress((void**)&pa,   g_pa);
    cudaGetSymbolAddress((void**)&pb,   g_pb);

    cudaFuncSetAttribute(k_knn_mma, cudaFuncAttributeMaxDynamicSharedMemorySize, KNN_SMEM);

    k_freq<<<1, 64>>>();

    // ---- stage 1 (N = 4096) ----
    k_prep<<<dim3(NB1, 4), 192>>>(x, xn, sqn);
    k_split2<<<dim3(NB1, 4), 192>>>(xn, pa, pb, NB1);
    k_knn_mma<<<dim3(NB1 / 128, 4), 256, KNN_SMEM>>>(pa, pb, sqn, idx, NB1);
    k_gather<<<dim3(NB1, 4), 192>>>(xn, idx, nb, NB1);
    k_lin<false><<<dim3(4 * NB1 / 64, 3), 256>>>(nb, xn, W1l, W1r, b1l, sg);
    k_wnorm<<<1, 192>>>(p1w, scal);
    k_scores<<<4 * NB1 / 8, 256>>>(sg, p1w, scal, sc);
    k_sort<<<4, 1024, NB1 * 8>>>(sc, perm, sv, NB1, NB2);
    k_gatherpool<<<dim3(NB2, 4), 192>>>(sg, perm, sv, pl, NB1, NB2);
    k_lin<true><<<dim3(4 * NB2 / 64, 3), 256>>>(pl, pl, ggam, ggam, gbeta, gd);

    // ---- stage 2 (N = 1024) ----
    k_sqn<<<dim3(NB2, 4), 192>>>(gd, sqn, NB2);
    k_split2<<<dim3(NB2, 4), 192>>>(gd, pa, pb, NB2);
    k_knn_mma<<<dim3(NB2 / 128, 4), 256, KNN_SMEM>>>(pa, pb, sqn, idx, NB2);
    k_gather<<<dim3(NB2, 4), 192>>>(gd, idx, nb, NB2);
    k_lin<false><<<dim3(4 * NB2 / 64, 3), 256>>>(nb, gd, W2l, W2r, b2l, sg2);
    k_wnorm<<<1, 192>>>(p2w, scal + 1);
    k_scores<<<4 * NB2 / 8, 256>>>(sg2, p2w, scal + 1, sc);
    k_sort<<<4, 1024, NB2 * 8>>>(sc, perm, sv, NB2, 256);
    k_gatherpool<<<dim3(256, 4), 192>>>(sg2, perm, sv, pl2, NB2, 256);
    k_final<<<dim3(256, 4), 192>>>(pl2, out);
}

// round 10
// speedup vs baseline: 1.3698x; 1.0338x over previous
#include <cuda_runtime.h>
#include <cuda_fp16.h>
#include <math.h>
#include <stdint.h>

#define CC 192
#define NB1 4096
#define NB2 1024

// ---------------- scratch (device globals; no allocation) ----------------
__device__ float d_freq[48];
__device__ float g_xn[4 * NB1 * CC];
__device__ float g_nb[4 * NB1 * CC];
__device__ float g_sage[4 * NB1 * CC];
__device__ float g_pool[4 * NB2 * CC];
__device__ float g_gdn[4 * NB2 * CC];
__device__ float g_sage2[4 * NB2 * CC];
__device__ float g_pool2[4 * 256 * CC];
__device__ float g_sqn[4 * NB1];
__device__ int   g_idx[4 * NB1 * 9];
__device__ int   g_perm[4 * NB2];
__device__ float g_sv[4 * NB2];
__device__ float g_scores[4 * NB1];
__device__ float g_scal[2];
__device__ __half g_pa[4 * NB1 * CC];
__device__ __half g_pb[4 * NB1 * CC];

// ---------------- helpers (compute_100-portable) ----------------
__device__ __forceinline__ uint32_t smem_u32(const void* p) {
    uint32_t a;
    asm("{ .reg .u64 t; cvta.to.shared.u64 t, %1; cvt.u32.u64 %0, t; }" : "=r"(a) : "l"(p));
    return a;
}
__device__ __forceinline__ void ldsm4(uint32_t* r, uint32_t addr) {
    asm volatile("ldmatrix.sync.aligned.m8n8.x4.shared.b16 {%0,%1,%2,%3}, [%4];"
                 : "=r"(r[0]), "=r"(r[1]), "=r"(r[2]), "=r"(r[3]) : "r"(addr));
}
__device__ __forceinline__ void mma16816(float* d, const uint32_t* a,
                                         uint32_t b0, uint32_t b1) {
    asm volatile("mma.sync.aligned.m16n8k16.row.col.f32.f16.f16.f32 "
                 "{%0,%1,%2,%3}, {%4,%5,%6,%7}, {%8,%9}, {%0,%1,%2,%3};"
                 : "+f"(d[0]), "+f"(d[1]), "+f"(d[2]), "+f"(d[3])
                 : "r"(a[0]), "r"(a[1]), "r"(a[2]), "r"(a[3]), "r"(b0), "r"(b1));
}

// ---------------- positional-encoding frequency table ----------------
__global__ void k_freq() {
    int j = threadIdx.x;
    if (j < 48) d_freq[j] = (float)(1.0 / pow(10000.0, (double)(2 * j) / 96.0));
}

// ---------------- add pos-enc, build node features + sq norms ----------------
__global__ void k_prep(const float* __restrict__ x, float* __restrict__ xn,
                       float* __restrict__ sqn) {
    int n = blockIdx.x, b = blockIdx.y, c = threadIdx.x;
    int y = n >> 6, xw = n & 63;
    float v = x[(((size_t)b * CC + c) * 64 + y) * 64 + xw];
    float f, arg;
    if (c < 96) { f = d_freq[c >> 1];        arg = (float)y  * f; }
    else        { f = d_freq[(c - 96) >> 1]; arg = (float)xw * f; }
    v += (c & 1) ? cosf(arg) : sinf(arg);
    xn[((size_t)b * NB1 + n) * CC + c] = v;
    __shared__ float red[192];
    red[c] = v * v;
    __syncthreads();
    if (c < 64) red[c] += red[c + 64] + red[c + 128];
    __syncthreads();
    if (c < 32) {
        float s = red[c] + red[c + 32];
        for (int o = 16; o; o >>= 1) s += __shfl_down_sync(0xffffffffu, s, o);
        if (c == 0) sqn[b * NB1 + n] = s;
    }
}

// ---------------- generic squared-norm ----------------
__global__ void k_sqn(const float* __restrict__ xn, float* __restrict__ sqn, int N) {
    int n = blockIdx.x, b = blockIdx.y, c = threadIdx.x;
    float v = xn[((size_t)b * N + n) * CC + c];
    __shared__ float red[192];
    red[c] = v * v;
    __syncthreads();
    if (c < 64) red[c] += red[c + 64] + red[c + 128];
    __syncthreads();
    if (c < 32) {
        float s = red[c] + red[c + 32];
        for (int o = 16; o; o >>= 1) s += __shfl_down_sync(0xffffffffu, s, o);
        if (c == 0) sqn[b * N + n] = s;
    }
}

// ---------------- 2-way fp16 split ----------------
__global__ void k_split2(const float* __restrict__ xn, __half* __restrict__ pa,
                         __half* __restrict__ pb, int N) {
    size_t i = (((size_t)blockIdx.y * N + blockIdx.x) * CC) + threadIdx.x;
    float v = xn[i];
    __half a = __float2half_rn(v);
    float r = v - __half2float(a);
    pa[i] = a; pb[i] = __float2half_rn(r);
}

// ---------------- mma.sync kNN v6: fp16 x2, bb term dropped (3 GEMM passes) ----------------
#define A_STRIDE 400
#define A_PLANE  (128 * A_STRIDE)           // 51200
#define OFF_B    (2 * A_PLANE)              // 102400
#define BBUF     (64 * A_STRIDE)            // 25600 per buffer (x3)
#define OFF_SQ   (OFF_B + 3 * BBUF)         // 179200
#define KNN_SMEM (OFF_SQ + 512)             // 179712

__device__ __forceinline__ void issue_b(uint32_t dstBase, const __half* plane,
                                        int colBase, int tid) {
    const char* g = (const char*)(plane + (size_t)colBase * CC);
#pragma unroll
    for (int t = 0; t < 6; t++) {
        int i = tid + t * 256;
        int row = i / 24, j = i - row * 24;
        uint32_t d = dstBase + row * A_STRIDE + j * 16;
        asm volatile("cp.async.cg.shared.global [%0], [%1], 16;"
                     :: "r"(d), "l"(g + row * 384 + j * 16));
    }
    asm volatile("cp.async.commit_group;" ::: "memory");
}

// One B plane vs NA A planes: per k-chunk load 4 B frags + NA A frags.
template<int NA>
__device__ __forceinline__ void gemm_group(float (*acc)[4], uint32_t aBase, uint32_t bBase) {
#pragma unroll
    for (int kk = 0; kk < 192; kk += 16) {
        uint32_t bq[4][4];
#pragma unroll
        for (int n2 = 0; n2 < 4; n2++)
            ldsm4(bq[n2], bBase + (n2 << 4) * A_STRIDE + kk * 2);
#pragma unroll
        for (int ap = 0; ap < NA; ap++) {
            uint32_t a[4];
            ldsm4(a, aBase + ap * A_PLANE + kk * 2);
#pragma unroll
            for (int n2 = 0; n2 < 4; n2++) {
                mma16816(acc[2 * n2],     a, bq[n2][0], bq[n2][1]);
                mma16816(acc[2 * n2 + 1], a, bq[n2][2], bq[n2][3]);
            }
        }
    }
}

__global__ void __launch_bounds__(256, 1)
k_knn_mma(const __half* __restrict__ pa, const __half* __restrict__ pb,
          const float* __restrict__ sqn, int* __restrict__ idxOut, int N) {
    extern __shared__ char sm[];
    const uint32_t smb = smem_u32(sm);
    const int tid = threadIdx.x, warp = tid >> 5, lane = tid & 31;
    const int b = blockIdx.y, rowBase = blockIdx.x << 7;
    const __half* P[2] = { pa + (size_t)b * N * CC, pb + (size_t)b * N * CC };
    const float* SQ = sqn + (size_t)b * N;
    float* sqs = (float*)(sm + OFF_SQ);

    // prologue: loads for steps 0 (plane0) and 1 (plane1), buffers 0 and 1
    issue_b(smb + OFF_B, P[0], 0, tid);
    issue_b(smb + OFF_B + BBUF, P[1], 0, tid);

    // resident A: 2 planes, 400B row stride (ldmatrix conflict-free)
#pragma unroll 1
    for (int p = 0; p < 2; p++) {
        const uint4* gp = (const uint4*)(P[p] + (size_t)rowBase * CC);
        for (int i = tid; i < 128 * 24; i += 256) {
            int row = i / 24, j = i - row * 24;
            *(uint4*)(sm + p * A_PLANE + row * A_STRIDE + j * 16) = gp[i];
        }
    }

    const int strip = warp << 4;
    const int r0 = strip + (lane >> 2);
    const uint32_t aBase = smb + (strip + (lane & 15)) * A_STRIDE + (((uint32_t)lane >> 4) << 4);
    const uint32_t bOff  = ((lane & 7) + ((lane >> 4) << 3)) * A_STRIDE + (((lane >> 3) & 1) << 4);

    const float sr0 = SQ[rowBase + r0], sr1 = SQ[rowBase + r0 + 8];

    float hd0[9], hd1[9]; int hi0[9], hi1[9];
#pragma unroll
    for (int q = 0; q < 9; q++) {
        hd0[q] = 3.4e38f; hi0[q] = 0x7fffffff;
        hd1[q] = 3.4e38f; hi1[q] = 0x7fffffff;
    }

    float acc[8][4];
    const int nsub = N >> 6, steps = nsub * 2;

#pragma unroll 1
    for (int step = 0; step < steps; step++) {
        const int sub = step >> 1, p = step & 1;
        asm volatile("cp.async.wait_group 1;" ::: "memory");
        __syncthreads();
        {   // issue load for step+2 (buffer (step+2)%3, plane (step+2)&1)
            int s2 = step + 2;
            if (s2 < steps)
                issue_b(smb + OFF_B + (s2 % 3) * BBUF, P[s2 & 1], (s2 >> 1) << 6, tid);
        }
        if (p == 0) {
            if (tid < 64) sqs[(sub & 1) * 64 + tid] = SQ[(sub << 6) + tid];
#pragma unroll
            for (int n = 0; n < 8; n++)
#pragma unroll
                for (int j = 0; j < 4; j++) acc[n][j] = 0.f;
        }
        const uint32_t bBase = smb + OFF_B + (step % 3) * BBUF + bOff;
        if (p == 0) {
            gemm_group<2>(acc, aBase, bBase);          // aa + ba
        } else {
            gemm_group<1>(acc, aBase, bBase);          // ab   (bb dropped: <=2^-22 rel)
            // ---- selection over this 64-col subtile ----
            const float* sq = sqs + (sub & 1) * 64;
            const int colBase = sub << 6;
#pragma unroll 1
            for (int n = 0; n < 8; n++) {
#pragma unroll
                for (int j = 0; j < 2; j++) {
                    int col = (n << 3) + ((lane & 3) << 1) + j;
                    float sc = sq[col];
                    int gcol = colBase + col;
                    float dv0 = fmaf(-2.f, acc[n][j], sr0 + sc);
                    if (dv0 < hd0[8]) {
                        hd0[8] = dv0; hi0[8] = gcol;
#pragma unroll
                        for (int q = 8; q > 0; q--) {
                            if (hd0[q - 1] > dv0) {
                                float td = hd0[q-1]; hd0[q-1] = hd0[q]; hd0[q] = td;
                                int   ti = hi0[q-1]; hi0[q-1] = hi0[q]; hi0[q] = ti;
                            } else break;
                        }
                    }
                    float dv1 = fmaf(-2.f, acc[n][2 + j], sr1 + sc);
                    if (dv1 < hd1[8]) {
                        hd1[8] = dv1; hi1[8] = gcol;
#pragma unroll
                        for (int q = 8; q > 0; q--) {
                            if (hd1[q - 1] > dv1) {
                                float td = hd1[q-1]; hd1[q-1] = hd1[q]; hd1[q] = td;
                                int   ti = hi1[q-1]; hi1[q-1] = hi1[q]; hi1[q] = ti;
                            } else break;
                        }
                    }
                }
            }
        }
    }

    // ---- merge 4 partial lists per row (lexicographic on (d, idx)) ----
    __syncthreads();
    float* md = (float*)(sm + OFF_B);            // [128][4][9] dists
    int*   mi = (int*)(sm + OFF_B + 18432);      // [128][4][9] idxs
    const int part = lane & 3;
#pragma unroll
    for (int q = 0; q < 9; q++) {
        md[(r0 * 4 + part) * 9 + q] = hd0[q];
        mi[(r0 * 4 + part) * 9 + q] = hi0[q];
        md[((r0 + 8) * 4 + part) * 9 + q] = hd1[q];
        mi[((r0 + 8) * 4 + part) * 9 + q] = hi1[q];
    }
    __syncthreads();
    if (part == 0) {
#pragma unroll 1
        for (int rr = 0; rr < 2; rr++) {
            int row = r0 + rr * 8;
            int p4[4] = {0, 0, 0, 0};
            size_t ob = ((size_t)b * N + rowBase + row) * 9;
            for (int q = 0; q < 9; q++) {
                float bd_ = 3.5e38f; int bi = 0x7fffffff, bm = 0;
#pragma unroll
                for (int m = 0; m < 4; m++) {
                    if (p4[m] < 9) {
                        float dv = md[(row * 4 + m) * 9 + p4[m]];
                        int   iv = mi[(row * 4 + m) * 9 + p4[m]];
                        if (dv < bd_ || (dv == bd_ && iv < bi)) { bd_ = dv; bi = iv; bm = m; }
                    }
                }
                idxOut[ob + q] = bi;
                p4[bm]++;
            }
        }
    }
}

// ---------------- gather + mean over 9 neighbors ----------------
__global__ void k_gather(const float* __restrict__ xn, const int* __restrict__ idx,
                         float* __restrict__ out, int N) {
    __shared__ int sid[9];
    int n = blockIdx.x, b = blockIdx.y, c = threadIdx.x;
    if (c < 9) sid[c] = idx[((size_t)b * N + n) * 9 + c];
    __syncthreads();
    const float* X = xn + (size_t)b * N * CC;
    float s = 0.f;
#pragma unroll
    for (int k = 0; k < 9; k++) s += X[(size_t)sid[k] * CC + c];
    out[((size_t)b * N + n) * CC + c] = s / 9.0f;
}

// ---------------- unified SAGE / GDN GEMM ----------------
template<bool GDN>
__global__ void k_lin(const float* __restrict__ A1, const float* __restrict__ A2,
                      const float* __restrict__ W1, const float* __restrict__ W2,
                      const float* __restrict__ bias, float* __restrict__ out) {
    int rowBase = blockIdx.x << 6, oBase = blockIdx.y << 6;
    __shared__ __align__(16) float A1s[16][68], A2s[16][68], W1s[16][68], W2s[16][68];
    int tid = threadIdx.x, ty = tid >> 4, tx = tid & 15;
    int lr = tid >> 2, lk = (tid & 3) << 2;
    float acc[4][4] = {};
    for (int kk = 0; kk < 192; kk += 16) {
        float4 a1 = *(const float4*)(A1 + (size_t)(rowBase + lr) * CC + kk + lk);
        float4 w1 = *(const float4*)(W1 + (size_t)(oBase + lr) * CC + kk + lk);
        float4 a2, w2;
        if (!GDN) {
            a2 = *(const float4*)(A2 + (size_t)(rowBase + lr) * CC + kk + lk);
            w2 = *(const float4*)(W2 + (size_t)(oBase + lr) * CC + kk + lk);
        }
        __syncthreads();
        if (GDN) { a1.x *= a1.x; a1.y *= a1.y; a1.z *= a1.z; a1.w *= a1.w; }
        A1s[lk+0][lr]=a1.x; A1s[lk+1][lr]=a1.y; A1s[lk+2][lr]=a1.z; A1s[lk+3][lr]=a1.w;
        W1s[lk+0][lr]=w1.x; W1s[lk+1][lr]=w1.y; W1s[lk+2][lr]=w1.z; W1s[lk+3][lr]=w1.w;
        if (!GDN) {
            A2s[lk+0][lr]=a2.x; A2s[lk+1][lr]=a2.y; A2s[lk+2][lr]=a2.z; A2s[lk+3][lr]=a2.w;
            W2s[lk+0][lr]=w2.x; W2s[lk+1][lr]=w2.y; W2s[lk+2][lr]=w2.z; W2s[lk+3][lr]=w2.w;
        }
        __syncthreads();
#pragma unroll
        for (int k = 0; k < 16; k++) {
            float4 xa = *(const float4*)&A1s[k][ty << 2];
            float4 u  = *(const float4*)&W1s[k][tx << 2];
            acc[0][0]+=xa.x*u.x; acc[0][1]+=xa.x*u.y; acc[0][2]+=xa.x*u.z; acc[0][3]+=xa.x*u.w;
            acc[1][0]+=xa.y*u.x; acc[1][1]+=xa.y*u.y; acc[1][2]+=xa.y*u.z; acc[1][3]+=xa.y*u.w;
            acc[2][0]+=xa.z*u.x; acc[2][1]+=xa.z*u.y; acc[2][2]+=xa.z*u.z; acc[2][3]+=xa.z*u.w;
            acc[3][0]+=xa.w*u.x; acc[3][1]+=xa.w*u.y; acc[3][2]+=xa.w*u.z; acc[3][3]+=xa.w*u.w;
            if (!GDN) {
                float4 xb = *(const float4*)&A2s[k][ty << 2];
                float4 v  = *(const float4*)&W2s[k][tx << 2];
                acc[0][0]+=xb.x*v.x; acc[0][1]+=xb.x*v.y; acc[0][2]+=xb.x*v.z; acc[0][3]+=xb.x*v.w;
                acc[1][0]+=xb.y*v.x; acc[1][1]+=xb.y*v.y; acc[1][2]+=xb.y*v.z; acc[1][3]+=xb.y*v.w;
                acc[2][0]+=xb.z*v.x; acc[2][1]+=xb.z*v.y; acc[2][2]+=xb.z*v.z; acc[2][3]+=xb.z*v.w;
                acc[3][0]+=xb.w*v.x; acc[3][1]+=xb.w*v.y; acc[3][2]+=xb.w*v.z; acc[3][3]+=xb.w*v.w;
            }
        }
    }
#pragma unroll
    for (int i = 0; i < 4; i++)
#pragma unroll
        for (int j = 0; j < 4; j++) {
            int oc = oBase + (tx << 2) + j;
            size_t off = (size_t)(rowBase + (ty << 2) + i) * CC + oc;
            if (GDN) out[off] = A1[off] * rsqrtf(acc[i][j] + bias[oc]);
            else     out[off] = acc[i][j] + bias[oc];
        }
}

// ---------------- ||w|| ----------------
__global__ void k_wnorm(const float* __restrict__ w, float* __restrict__ outp) {
    int c = threadIdx.x;
    __shared__ float red[192];
    float v = w[c];
    red[c] = v * v;
    __syncthreads();
    if (c < 64) red[c] += red[c + 64] + red[c + 128];
    __syncthreads();
    if (c < 32) {
        float s = red[c] + red[c + 32];
        for (int o = 16; o; o >>= 1) s += __shfl_down_sync(0xffffffffu, s, o);
        if (c == 0) *outp = sqrtf(s);
    }
}

// ---------------- pooling scores ----------------
__global__ void k_scores(const float* __restrict__ xn, const float* __restrict__ w,
                         const float* __restrict__ nrm, float* __restrict__ s) {
    int gw = (blockIdx.x << 3) + (threadIdx.x >> 5);
    int lane = threadIdx.x & 31;
    const float* row = xn + (size_t)gw * CC;
    float acc = 0.f;
#pragma unroll
    for (int c = lane; c < CC; c += 32) acc += row[c] * w[c];
    for (int o = 16; o; o >>= 1) acc += __shfl_down_sync(0xffffffffu, acc, o);
    if (!lane) s[gw] = tanhf(acc / nrm[0]);
}

// ---------------- stable bitonic sort: (score desc, idx asc) ----------------
__global__ void k_sort(const float* __restrict__ s, int* __restrict__ perm,
                       float* __restrict__ sv, int N, int KEEP) {
    extern __shared__ unsigned long long key[];
    int b = blockIdx.x, tid = threadIdx.x, nt = blockDim.x;
    for (int i = tid; i < N; i += nt) {
        unsigned u = __float_as_uint(s[b * N + i]);
        u = (u & 0x80000000u) ? ~u : (u | 0x80000000u);
        u = ~u;
        key[i] = ((unsigned long long)u << 32) | (unsigned)i;
    }
    __syncthreads();
    for (int k2 = 2; k2 <= N; k2 <<= 1)
        for (int j = k2 >> 1; j > 0; j >>= 1) {
            for (int i = tid; i < N; i += nt) {
                int ixj = i ^ j;
                if (ixj > i) {
                    unsigned long long a = key[i], c = key[ixj];
                    bool up = ((i & k2) == 0);
                    if ((a > c) == up) { key[i] = c; key[ixj] = a; }
                }
            }
            __syncthreads();
        }
    for (int i = tid; i < KEEP; i += nt) {
        unsigned long long a = key[i];
        unsigned idx = (unsigned)(a & 0xffffffffu);
        unsigned u = ~(unsigned)(a >> 32);
        u = (u & 0x80000000u) ? (u & 0x7fffffffu) : ~u;
        perm[b * KEEP + i] = (int)idx;
        sv[b * KEEP + i] = __uint_as_float(u);
    }
}

// ---------------- gather kept nodes, gate by score ----------------
__global__ void k_gatherpool(const float* __restrict__ in, const int* __restrict__ perm,
                             const float* __restrict__ sv, float* __restrict__ out,
                             int N, int KEEP) {
    int i = blockIdx.x, b = blockIdx.y, c = threadIdx.x;
    int p = perm[b * KEEP + i];
    out[((size_t)b * KEEP + i) * CC + c] = in[((size_t)b * N + p) * CC + c] * sv[b * KEEP + i];
}

// ---------------- final NHWC->NCHW ----------------
__global__ void k_final(const float* __restrict__ in, float* __restrict__ out) {
    int n = blockIdx.x, b = blockIdx.y, c = threadIdx.x;
    out[(((size_t)b * CC + c) * 16 + (n >> 4)) * 16 + (n & 15)] =
        in[((size_t)b * 256 + n) * CC + c];
}

// ---------------- launch ----------------
extern "C" void kernel_launch(void* const* d_in, const int* in_sizes, int n_in,
                              void* d_out, int out_size) {
    const float* x     = (const float*)d_in[0];
    const float* W1l   = (const float*)d_in[1];
    const float* b1l   = (const float*)d_in[2];
    const float* W1r   = (const float*)d_in[3];
    const float* p1w   = (const float*)d_in[4];
    const float* gbeta = (const float*)d_in[5];
    const float* ggam  = (const float*)d_in[6];
    const float* W2l   = (const float*)d_in[7];
    const float* b2l   = (const float*)d_in[8];
    const float* W2r   = (const float*)d_in[9];
    const float* p2w   = (const float*)d_in[10];
    float* out = (float*)d_out;

    float *xn, *nb, *sg, *pl, *gd, *sg2, *pl2, *sqn, *sv, *sc, *scal;
    int *idx, *perm;
    __half *pa, *pb;
    cudaGetSymbolAddress((void**)&xn,   g_xn);
    cudaGetSymbolAddress((void**)&nb,   g_nb);
    cudaGetSymbolAddress((void**)&sg,   g_sage);
    cudaGetSymbolAddress((void**)&pl,   g_pool);
    cudaGetSymbolAddress((void**)&gd,   g_gdn);
    cudaGetSymbolAddress((void**)&sg2,  g_sage2);
    cudaGetSymbolAddress((void**)&pl2,  g_pool2);
    cudaGetSymbolAddress((void**)&sqn,  g_sqn);
    cudaGetSymbolAddress((void**)&sv,   g_sv);
    cudaGetSymbolAddress((void**)&sc,   g_scores);
    cudaGetSymbolAddress((void**)&scal, g_scal);
    cudaGetSymbolAddress((void**)&idx,  g_idx);
    cudaGetSymbolAddress((void**)&perm, g_perm);
    cudaGetSymbolAddress((void**)&pa,   g_pa);
    cudaGetSymbolAddress((void**)&pb,   g_pb);

    cudaFuncSetAttribute(k_knn_mma, cudaFuncAttributeMaxDynamicSharedMemorySize, KNN_SMEM);

    k_freq<<<1, 64>>>();

    // ---- stage 1 (N = 4096) ----
    k_prep<<<dim3(NB1, 4), 192>>>(x, xn, sqn);
    k_split2<<<dim3(NB1, 4), 192>>>(xn, pa, pb, NB1);
    k_knn_mma<<<dim3(NB1 / 128, 4), 256, KNN_SMEM>>>(pa, pb, sqn, idx, NB1);
    k_gather<<<dim3(NB1, 4), 192>>>(xn, idx, nb, NB1);
    k_lin<false><<<dim3(4 * NB1 / 64, 3), 256>>>(nb, xn, W1l, W1r, b1l, sg);
    k_wnorm<<<1, 192>>>(p1w, scal);
    k_scores<<<4 * NB1 / 8, 256>>>(sg, p1w, scal, sc);
    k_sort<<<4, 1024, NB1 * 8>>>(sc, perm, sv, NB1, NB2);
    k_gatherpool<<<dim3(NB2, 4), 192>>>(sg, perm, sv, pl, NB1, NB2);
    k_lin<true><<<dim3(4 * NB2 / 64, 3), 256>>>(pl, pl, ggam, ggam, gbeta, gd);

    // ---- stage 2 (N = 1024) ----
    k_sqn<<<dim3(NB2, 4), 192>>>(gd, sqn, NB2);
    k_split2<<<dim3(NB2, 4), 192>>>(gd, pa, pb, NB2);
    k_knn_mma<<<dim3(NB2 / 128, 4), 256, KNN_SMEM>>>(pa, pb, sqn, idx, NB2);
    k_gather<<<dim3(NB2, 4), 192>>>(gd, idx, nb, NB2);
    k_lin<false><<<dim3(4 * NB2 / 64, 3), 256>>>(nb, gd, W2l, W2r, b2l, sg2);
    k_wnorm<<<1, 192>>>(p2w, scal + 1);
    k_scores<<<4 * NB2 / 8, 256>>>(sg2, p2w, scal + 1, sc);
    k_sort<<<4, 1024, NB2 * 8>>>(sc, perm, sv, NB2, 256);
    k_gatherpool<<<dim3(256, 4), 192>>>(sg2, perm, sv, pl2, NB2, 256);
    k_final<<<dim3(256, 4), 192>>>(pl2, out);
}

// round 11
// speedup vs baseline: 1.5660x; 1.1433x over previous
#include <cuda_runtime.h>
#include <cuda_fp16.h>
#include <math.h>
#include <stdint.h>

#define CC 192
#define NB1 4096
#define NB2 1024

// ---------------- scratch (device globals; no allocation) ----------------
__device__ float d_freq[48];
__device__ float g_xn[4 * NB1 * CC];
__device__ float g_nb[4 * NB1 * CC];
__device__ float g_sage[4 * NB1 * CC];
__device__ float g_pool[4 * NB2 * CC];
__device__ float g_gdn[4 * NB2 * CC];
__device__ float g_sage2[4 * NB2 * CC];
__device__ float g_pool2[4 * 256 * CC];
__device__ float g_sqn[4 * NB1];
__device__ int   g_idx[4 * NB1 * 9];
__device__ int   g_perm[4 * NB2];
__device__ float g_sv[4 * NB2];
__device__ float g_scores[4 * NB1];
__device__ float g_scal[2];
__device__ __half g_pa[4 * NB1 * CC];
__device__ __half g_pb[4 * NB1 * CC];
__device__ float g_pdist[4 * NB1 * 4 * 9];
__device__ int   g_pidx[4 * NB1 * 4 * 9];

// ---------------- helpers (compute_100-portable) ----------------
__device__ __forceinline__ uint32_t smem_u32(const void* p) {
    uint32_t a;
    asm("{ .reg .u64 t; cvta.to.shared.u64 t, %1; cvt.u32.u64 %0, t; }" : "=r"(a) : "l"(p));
    return a;
}
__device__ __forceinline__ void ldsm4(uint32_t* r, uint32_t addr) {
    asm volatile("ldmatrix.sync.aligned.m8n8.x4.shared.b16 {%0,%1,%2,%3}, [%4];"
                 : "=r"(r[0]), "=r"(r[1]), "=r"(r[2]), "=r"(r[3]) : "r"(addr));
}
__device__ __forceinline__ void mma16816(float* d, const uint32_t* a,
                                         uint32_t b0, uint32_t b1) {
    asm volatile("mma.sync.aligned.m16n8k16.row.col.f32.f16.f16.f32 "
                 "{%0,%1,%2,%3}, {%4,%5,%6,%7}, {%8,%9}, {%0,%1,%2,%3};"
                 : "+f"(d[0]), "+f"(d[1]), "+f"(d[2]), "+f"(d[3])
                 : "r"(a[0]), "r"(a[1]), "r"(a[2]), "r"(a[3]), "r"(b0), "r"(b1));
}

// ---------------- positional-encoding frequency table ----------------
__global__ void k_freq() {
    int j = threadIdx.x;
    if (j < 48) d_freq[j] = (float)(1.0 / pow(10000.0, (double)(2 * j) / 96.0));
}

// ---------------- add pos-enc, build node features + sq norms ----------------
__global__ void k_prep(const float* __restrict__ x, float* __restrict__ xn,
                       float* __restrict__ sqn) {
    int n = blockIdx.x, b = blockIdx.y, c = threadIdx.x;
    int y = n >> 6, xw = n & 63;
    float v = x[(((size_t)b * CC + c) * 64 + y) * 64 + xw];
    float f, arg;
    if (c < 96) { f = d_freq[c >> 1];        arg = (float)y  * f; }
    else        { f = d_freq[(c - 96) >> 1]; arg = (float)xw * f; }
    v += (c & 1) ? cosf(arg) : sinf(arg);
    xn[((size_t)b * NB1 + n) * CC + c] = v;
    __shared__ float red[192];
    red[c] = v * v;
    __syncthreads();
    if (c < 64) red[c] += red[c + 64] + red[c + 128];
    __syncthreads();
    if (c < 32) {
        float s = red[c] + red[c + 32];
        for (int o = 16; o; o >>= 1) s += __shfl_down_sync(0xffffffffu, s, o);
        if (c == 0) sqn[b * NB1 + n] = s;
    }
}

// ---------------- generic squared-norm ----------------
__global__ void k_sqn(const float* __restrict__ xn, float* __restrict__ sqn, int N) {
    int n = blockIdx.x, b = blockIdx.y, c = threadIdx.x;
    float v = xn[((size_t)b * N + n) * CC + c];
    __shared__ float red[192];
    red[c] = v * v;
    __syncthreads();
    if (c < 64) red[c] += red[c + 64] + red[c + 128];
    __syncthreads();
    if (c < 32) {
        float s = red[c] + red[c + 32];
        for (int o = 16; o; o >>= 1) s += __shfl_down_sync(0xffffffffu, s, o);
        if (c == 0) sqn[b * N + n] = s;
    }
}

// ---------------- 2-way fp16 split ----------------
__global__ void k_split2(const float* __restrict__ xn, __half* __restrict__ pa,
                         __half* __restrict__ pb, int N) {
    size_t i = (((size_t)blockIdx.y * N + blockIdx.x) * CC) + threadIdx.x;
    float v = xn[i];
    __half a = __float2half_rn(v);
    float r = v - __half2float(a);
    pa[i] = a; pb[i] = __float2half_rn(r);
}

// ---------------- mma.sync kNN v7: reg-pipelined k-loop, col-split ----------------
#define A_STRIDE 400
#define A_PLANE  (128 * A_STRIDE)           // 51200
#define OFF_B    (2 * A_PLANE)              // 102400
#define BBUF     (64 * A_STRIDE)            // 25600 per buffer (x3)
#define OFF_SQ   (OFF_B + 3 * BBUF)         // 179200
#define KNN_SMEM (OFF_SQ + 512)             // 179712

__device__ __forceinline__ void issue_b(uint32_t dstBase, const __half* plane,
                                        int colBase, int tid) {
    const char* g = (const char*)(plane + (size_t)colBase * CC);
#pragma unroll
    for (int t = 0; t < 6; t++) {
        int i = tid + t * 256;
        int row = i / 24, j = i - row * 24;
        uint32_t d = dstBase + row * A_STRIDE + j * 16;
        asm volatile("cp.async.cg.shared.global [%0], [%1], 16;"
                     :: "r"(d), "l"(g + row * 384 + j * 16));
    }
    asm volatile("cp.async.commit_group;" ::: "memory");
}

// Register-double-buffered k-loop: fragments for chunk kk+1 are loaded BEFORE
// the MMAs of chunk kk (volatile asm keeps source order => latency hidden).
template<int NA>
__device__ __forceinline__ void gemm_group(float (*acc)[4], uint32_t aBase, uint32_t bBase) {
    uint32_t bq[2][4][4];
    uint32_t av[2][NA][4];
#pragma unroll
    for (int n2 = 0; n2 < 4; n2++) ldsm4(bq[0][n2], bBase + (n2 << 4) * A_STRIDE);
#pragma unroll
    for (int ap = 0; ap < NA; ap++) ldsm4(av[0][ap], aBase + ap * A_PLANE);
#pragma unroll
    for (int kk = 0; kk < 12; kk++) {
        const int cur = kk & 1, nxt = cur ^ 1;
        if (kk < 11) {
#pragma unroll
            for (int n2 = 0; n2 < 4; n2++)
                ldsm4(bq[nxt][n2], bBase + (n2 << 4) * A_STRIDE + (kk + 1) * 32);
#pragma unroll
            for (int ap = 0; ap < NA; ap++)
                ldsm4(av[nxt][ap], aBase + ap * A_PLANE + (kk + 1) * 32);
        }
#pragma unroll
        for (int ap = 0; ap < NA; ap++)
#pragma unroll
            for (int n2 = 0; n2 < 4; n2++) {
                mma16816(acc[2 * n2],     av[cur][ap], bq[cur][n2][0], bq[cur][n2][1]);
                mma16816(acc[2 * n2 + 1], av[cur][ap], bq[cur][n2][2], bq[cur][n2][3]);
            }
    }
}

// grid: (rowTiles, batch, nparts). Each CTA scans cols [part*span, (part+1)*span).
__global__ void __launch_bounds__(256, 1)
k_knn_mma(const __half* __restrict__ pa, const __half* __restrict__ pb,
          const float* __restrict__ sqn, float* __restrict__ pdOut,
          int* __restrict__ piOut, int N, int nparts) {
    extern __shared__ char sm[];
    const uint32_t smb = smem_u32(sm);
    const int tid = threadIdx.x, warp = tid >> 5, lane = tid & 31;
    const int b = blockIdx.y, rowBase = blockIdx.x << 7, part = blockIdx.z;
    const int span = N / nparts, colStart = part * span;
    const __half* P[2] = { pa + (size_t)b * N * CC, pb + (size_t)b * N * CC };
    const float* SQ = sqn + (size_t)b * N;
    float* sqs = (float*)(sm + OFF_SQ);

    // prologue: loads for steps 0 (plane0) and 1 (plane1), buffers 0 and 1
    issue_b(smb + OFF_B, P[0], colStart, tid);
    issue_b(smb + OFF_B + BBUF, P[1], colStart, tid);

    // resident A: 2 planes, 400B row stride (ldmatrix conflict-free)
#pragma unroll 1
    for (int p = 0; p < 2; p++) {
        const uint4* gp = (const uint4*)(P[p] + (size_t)rowBase * CC);
        for (int i = tid; i < 128 * 24; i += 256) {
            int row = i / 24, j = i - row * 24;
            *(uint4*)(sm + p * A_PLANE + row * A_STRIDE + j * 16) = gp[i];
        }
    }

    const int strip = warp << 4;
    const int r0 = strip + (lane >> 2);
    const uint32_t aBase = smb + (strip + (lane & 15)) * A_STRIDE + (((uint32_t)lane >> 4) << 4);
    const uint32_t bOff  = ((lane & 7) + ((lane >> 4) << 3)) * A_STRIDE + (((lane >> 3) & 1) << 4);

    const float sr0 = SQ[rowBase + r0], sr1 = SQ[rowBase + r0 + 8];

    float hd0[9], hd1[9]; int hi0[9], hi1[9];
#pragma unroll
    for (int q = 0; q < 9; q++) {
        hd0[q] = 3.4e38f; hi0[q] = 0x7fffffff;
        hd1[q] = 3.4e38f; hi1[q] = 0x7fffffff;
    }

    float acc[8][4];
    const int nsub = span >> 6, steps = nsub * 2;

#pragma unroll 1
    for (int step = 0; step < steps; step++) {
        const int sub = step >> 1, p = step & 1;
        const int colBase = colStart + (sub << 6);
        asm volatile("cp.async.wait_group 1;" ::: "memory");
        __syncthreads();
        {   // issue load for step+2
            int s2 = step + 2;
            if (s2 < steps)
                issue_b(smb + OFF_B + (s2 % 3) * BBUF, P[s2 & 1],
                        colStart + ((s2 >> 1) << 6), tid);
        }
        if (p == 0) {
            if (tid < 64) sqs[(sub & 1) * 64 + tid] = SQ[colBase + tid];
#pragma unroll
            for (int n = 0; n < 8; n++)
#pragma unroll
                for (int j = 0; j < 4; j++) acc[n][j] = 0.f;
        }
        const uint32_t bBase = smb + OFF_B + (step % 3) * BBUF + bOff;
        if (p == 0) {
            gemm_group<2>(acc, aBase, bBase);          // aa + ba
        } else {
            gemm_group<1>(acc, aBase, bBase);          // ab   (bb dropped: <=2^-22 rel)
            // ---- selection over this 64-col subtile ----
            const float* sq = sqs + (sub & 1) * 64;
#pragma unroll 1
            for (int n = 0; n < 8; n++) {
#pragma unroll
                for (int j = 0; j < 2; j++) {
                    int col = (n << 3) + ((lane & 3) << 1) + j;
                    float sc = sq[col];
                    int gcol = colBase + col;
                    float dv0 = fmaf(-2.f, acc[n][j], sr0 + sc);
                    if (dv0 < hd0[8]) {
                        hd0[8] = dv0; hi0[8] = gcol;
#pragma unroll
                        for (int q = 8; q > 0; q--) {
                            if (hd0[q - 1] > dv0) {
                                float td = hd0[q-1]; hd0[q-1] = hd0[q]; hd0[q] = td;
                                int   ti = hi0[q-1]; hi0[q-1] = hi0[q]; hi0[q] = ti;
                            } else break;
                        }
                    }
                    float dv1 = fmaf(-2.f, acc[n][2 + j], sr1 + sc);
                    if (dv1 < hd1[8]) {
                        hd1[8] = dv1; hi1[8] = gcol;
#pragma unroll
                        for (int q = 8; q > 0; q--) {
                            if (hd1[q - 1] > dv1) {
                                float td = hd1[q-1]; hd1[q-1] = hd1[q]; hd1[q] = td;
                                int   ti = hi1[q-1]; hi1[q-1] = hi1[q]; hi1[q] = ti;
                            } else break;
                        }
                    }
                }
            }
        }
    }

    // ---- merge 4 thread-partial lists per row -> per-CTA 9, store to part slot ----
    __syncthreads();
    float* md = (float*)(sm + OFF_B);            // [128][4][9] dists
    int*   mi = (int*)(sm + OFF_B + 18432);      // [128][4][9] idxs
    const int tp = lane & 3;
#pragma unroll
    for (int q = 0; q < 9; q++) {
        md[(r0 * 4 + tp) * 9 + q] = hd0[q];
        mi[(r0 * 4 + tp) * 9 + q] = hi0[q];
        md[((r0 + 8) * 4 + tp) * 9 + q] = hd1[q];
        mi[((r0 + 8) * 4 + tp) * 9 + q] = hi1[q];
    }
    __syncthreads();
    if (tp == 0) {
#pragma unroll 1
        for (int rr = 0; rr < 2; rr++) {
            int row = r0 + rr * 8;
            int p4[4] = {0, 0, 0, 0};
            size_t ob = (((size_t)b * N + rowBase + row) * nparts + part) * 9;
            for (int q = 0; q < 9; q++) {
                float bd_ = 3.5e38f; int bi = 0x7fffffff, bm = 0;
#pragma unroll
                for (int m = 0; m < 4; m++) {
                    if (p4[m] < 9) {
                        float dv = md[(row * 4 + m) * 9 + p4[m]];
                        int   iv = mi[(row * 4 + m) * 9 + p4[m]];
                        if (dv < bd_ || (dv == bd_ && iv < bi)) { bd_ = dv; bi = iv; bm = m; }
                    }
                }
                pdOut[ob + q] = bd_;
                piOut[ob + q] = bi;
                p4[bm]++;
            }
        }
    }
}

// ---------------- merge P per-part lists -> final 9 indices ----------------
__global__ void k_merge(const float* __restrict__ pd, const int* __restrict__ pi,
                        int* __restrict__ idxOut, int N, int P) {
    int row = blockIdx.x * 128 + threadIdx.x, b = blockIdx.y;
    const float* d = pd + ((size_t)b * N + row) * P * 9;
    const int*   ii = pi + ((size_t)b * N + row) * P * 9;
    int pp[4] = {0, 0, 0, 0};
    size_t ob = ((size_t)b * N + row) * 9;
#pragma unroll 1
    for (int q = 0; q < 9; q++) {
        float bd_ = 3.5e38f; int bi = 0x7fffffff, bm = 0;
        for (int m = 0; m < P; m++) {
            float dv = d[m * 9 + pp[m]];
            int   iv = ii[m * 9 + pp[m]];
            if (dv < bd_ || (dv == bd_ && iv < bi)) { bd_ = dv; bi = iv; bm = m; }
        }
        idxOut[ob + q] = bi;
        pp[bm]++;
    }
}

// ---------------- gather + mean over 9 neighbors ----------------
__global__ void k_gather(const float* __restrict__ xn, const int* __restrict__ idx,
                         float* __restrict__ out, int N) {
    __shared__ int sid[9];
    int n = blockIdx.x, b = blockIdx.y, c = threadIdx.x;
    if (c < 9) sid[c] = idx[((size_t)b * N + n) * 9 + c];
    __syncthreads();
    const float* X = xn + (size_t)b * N * CC;
    float s = 0.f;
#pragma unroll
    for (int k = 0; k < 9; k++) s += X[(size_t)sid[k] * CC + c];
    out[((size_t)b * N + n) * CC + c] = s / 9.0f;
}

// ---------------- unified SAGE / GDN GEMM ----------------
template<bool GDN>
__global__ void k_lin(const float* __restrict__ A1, const float* __restrict__ A2,
                      const float* __restrict__ W1, const float* __restrict__ W2,
                      const float* __restrict__ bias, float* __restrict__ out) {
    int rowBase = blockIdx.x << 6, oBase = blockIdx.y << 6;
    __shared__ __align__(16) float A1s[16][68], A2s[16][68], W1s[16][68], W2s[16][68];
    int tid = threadIdx.x, ty = tid >> 4, tx = tid & 15;
    int lr = tid >> 2, lk = (tid & 3) << 2;
    float acc[4][4] = {};
    for (int kk = 0; kk < 192; kk += 16) {
        float4 a1 = *(const float4*)(A1 + (size_t)(rowBase + lr) * CC + kk + lk);
        float4 w1 = *(const float4*)(W1 + (size_t)(oBase + lr) * CC + kk + lk);
        float4 a2, w2;
        if (!GDN) {
            a2 = *(const float4*)(A2 + (size_t)(rowBase + lr) * CC + kk + lk);
            w2 = *(const float4*)(W2 + (size_t)(oBase + lr) * CC + kk + lk);
        }
        __syncthreads();
        if (GDN) { a1.x *= a1.x; a1.y *= a1.y; a1.z *= a1.z; a1.w *= a1.w; }
        A1s[lk+0][lr]=a1.x; A1s[lk+1][lr]=a1.y; A1s[lk+2][lr]=a1.z; A1s[lk+3][lr]=a1.w;
        W1s[lk+0][lr]=w1.x; W1s[lk+1][lr]=w1.y; W1s[lk+2][lr]=w1.z; W1s[lk+3][lr]=w1.w;
        if (!GDN) {
            A2s[lk+0][lr]=a2.x; A2s[lk+1][lr]=a2.y; A2s[lk+2][lr]=a2.z; A2s[lk+3][lr]=a2.w;
            W2s[lk+0][lr]=w2.x; W2s[lk+1][lr]=w2.y; W2s[lk+2][lr]=w2.z; W2s[lk+3][lr]=w2.w;
        }
        __syncthreads();
#pragma unroll
        for (int k = 0; k < 16; k++) {
            float4 xa = *(const float4*)&A1s[k][ty << 2];
            float4 u  = *(const float4*)&W1s[k][tx << 2];
            acc[0][0]+=xa.x*u.x; acc[0][1]+=xa.x*u.y; acc[0][2]+=xa.x*u.z; acc[0][3]+=xa.x*u.w;
            acc[1][0]+=xa.y*u.x; acc[1][1]+=xa.y*u.y; acc[1][2]+=xa.y*u.z; acc[1][3]+=xa.y*u.w;
            acc[2][0]+=xa.z*u.x; acc[2][1]+=xa.z*u.y; acc[2][2]+=xa.z*u.z; acc[2][3]+=xa.z*u.w;
            acc[3][0]+=xa.w*u.x; acc[3][1]+=xa.w*u.y; acc[3][2]+=xa.w*u.z; acc[3][3]+=xa.w*u.w;
            if (!GDN) {
                float4 xb = *(const float4*)&A2s[k][ty << 2];
                float4 v  = *(const float4*)&W2s[k][tx << 2];
                acc[0][0]+=xb.x*v.x; acc[0][1]+=xb.x*v.y; acc[0][2]+=xb.x*v.z; acc[0][3]+=xb.x*v.w;
                acc[1][0]+=xb.y*v.x; acc[1][1]+=xb.y*v.y; acc[1][2]+=xb.y*v.z; acc[1][3]+=xb.y*v.w;
                acc[2][0]+=xb.z*v.x; acc[2][1]+=xb.z*v.y; acc[2][2]+=xb.z*v.z; acc[2][3]+=xb.z*v.w;
                acc[3][0]+=xb.w*v.x; acc[3][1]+=xb.w*v.y; acc[3][2]+=xb.w*v.z; acc[3][3]+=xb.w*v.w;
            }
        }
    }
#pragma unroll
    for (int i = 0; i < 4; i++)
#pragma unroll
        for (int j = 0; j < 4; j++) {
            int oc = oBase + (tx << 2) + j;
            size_t off = (size_t)(rowBase + (ty << 2) + i) * CC + oc;
            if (GDN) out[off] = A1[off] * rsqrtf(acc[i][j] + bias[oc]);
            else     out[off] = acc[i][j] + bias[oc];
        }
}

// ---------------- ||w|| ----------------
__global__ void k_wnorm(const float* __restrict__ w, float* __restrict__ outp) {
    int c = threadIdx.x;
    __shared__ float red[192];
    float v = w[c];
    red[c] = v * v;
    __syncthreads();
    if (c < 64) red[c] += red[c + 64] + red[c + 128];
    __syncthreads();
    if (c < 32) {
        float s = red[c] + red[c + 32];
        for (int o = 16; o; o >>= 1) s += __shfl_down_sync(0xffffffffu, s, o);
        if (c == 0) *outp = sqrtf(s);
    }
}

// ---------------- pooling scores ----------------
__global__ void k_scores(const float* __restrict__ xn, const float* __restrict__ w,
                         const float* __restrict__ nrm, float* __restrict__ s) {
    int gw = (blockIdx.x << 3) + (threadIdx.x >> 5);
    int lane = threadIdx.x & 31;
    const float* row = xn + (size_t)gw * CC;
    float acc = 0.f;
#pragma unroll
    for (int c = lane; c < CC; c += 32) acc += row[c] * w[c];
    for (int o = 16; o; o >>= 1) acc += __shfl_down_sync(0xffffffffu, acc, o);
    if (!lane) s[gw] = tanhf(acc / nrm[0]);
}

// ---------------- stable bitonic sort: (score desc, idx asc) ----------------
__global__ void k_sort(const float* __restrict__ s, int* __restrict__ perm,
                       float* __restrict__ sv, int N, int KEEP) {
    extern __shared__ unsigned long long key[];
    int b = blockIdx.x, tid = threadIdx.x, nt = blockDim.x;
    for (int i = tid; i < N; i += nt) {
        unsigned u = __float_as_uint(s[b * N + i]);
        u = (u & 0x80000000u) ? ~u : (u | 0x80000000u);
        u = ~u;
        key[i] = ((unsigned long long)u << 32) | (unsigned)i;
    }
    __syncthreads();
    for (int k2 = 2; k2 <= N; k2 <<= 1)
        for (int j = k2 >> 1; j > 0; j >>= 1) {
            for (int i = tid; i < N; i += nt) {
                int ixj = i ^ j;
                if (ixj > i) {
                    unsigned long long a = key[i], c = key[ixj];
                    bool up = ((i & k2) == 0);
                    if ((a > c) == up) { key[i] = c; key[ixj] = a; }
                }
            }
            __syncthreads();
        }
    for (int i = tid; i < KEEP; i += nt) {
        unsigned long long a = key[i];
        unsigned idx = (unsigned)(a & 0xffffffffu);
        unsigned u = ~(unsigned)(a >> 32);
        u = (u & 0x80000000u) ? (u & 0x7fffffffu) : ~u;
        perm[b * KEEP + i] = (int)idx;
        sv[b * KEEP + i] = __uint_as_float(u);
    }
}

// ---------------- gather kept nodes, gate by score ----------------
__global__ void k_gatherpool(const float* __restrict__ in, const int* __restrict__ perm,
                             const float* __restrict__ sv, float* __restrict__ out,
                             int N, int KEEP) {
    int i = blockIdx.x, b = blockIdx.y, c = threadIdx.x;
    int p = perm[b * KEEP + i];
    out[((size_t)b * KEEP + i) * CC + c] = in[((size_t)b * N + p) * CC + c] * sv[b * KEEP + i];
}

// ---------------- final NHWC->NCHW ----------------
__global__ void k_final(const float* __restrict__ in, float* __restrict__ out) {
    int n = blockIdx.x, b = blockIdx.y, c = threadIdx.x;
    out[(((size_t)b * CC + c) * 16 + (n >> 4)) * 16 + (n & 15)] =
        in[((size_t)b * 256 + n) * CC + c];
}

// ---------------- launch ----------------
extern "C" void kernel_launch(void* const* d_in, const int* in_sizes, int n_in,
                              void* d_out, int out_size) {
    const float* x     = (const float*)d_in[0];
    const float* W1l   = (const float*)d_in[1];
    const float* b1l   = (const float*)d_in[2];
    const float* W1r   = (const float*)d_in[3];
    const float* p1w   = (const float*)d_in[4];
    const float* gbeta = (const float*)d_in[5];
    const float* ggam  = (const float*)d_in[6];
    const float* W2l   = (const float*)d_in[7];
    const float* b2l   = (const float*)d_in[8];
    const float* W2r   = (const float*)d_in[9];
    const float* p2w   = (const float*)d_in[10];
    float* out = (float*)d_out;

    float *xn, *nb, *sg, *pl, *gd, *sg2, *pl2, *sqn, *sv, *sc, *scal, *pd;
    int *idx, *perm, *pi;
    __half *pa, *pb;
    cudaGetSymbolAddress((void**)&xn,   g_xn);
    cudaGetSymbolAddress((void**)&nb,   g_nb);
    cudaGetSymbolAddress((void**)&sg,   g_sage);
    cudaGetSymbolAddress((void**)&pl,   g_pool);
    cudaGetSymbolAddress((void**)&gd,   g_gdn);
    cudaGetSymbolAddress((void**)&sg2,  g_sage2);
    cudaGetSymbolAddress((void**)&pl2,  g_pool2);
    cudaGetSymbolAddress((void**)&sqn,  g_sqn);
    cudaGetSymbolAddress((void**)&sv,   g_sv);
    cudaGetSymbolAddress((void**)&sc,   g_scores);
    cudaGetSymbolAddress((void**)&scal, g_scal);
    cudaGetSymbolAddress((void**)&idx,  g_idx);
    cudaGetSymbolAddress((void**)&perm, g_perm);
    cudaGetSymbolAddress((void**)&pa,   g_pa);
    cudaGetSymbolAddress((void**)&pb,   g_pb);
    cudaGetSymbolAddress((void**)&pd,   g_pdist);
    cudaGetSymbolAddress((void**)&pi,   g_pidx);

    cudaFuncSetAttribute(k_knn_mma, cudaFuncAttributeMaxDynamicSharedMemorySize, KNN_SMEM);

    k_freq<<<1, 64>>>();

    // ---- stage 1 (N = 4096) ----
    k_prep<<<dim3(NB1, 4), 192>>>(x, xn, sqn);
    k_split2<<<dim3(NB1, 4), 192>>>(xn, pa, pb, NB1);
    k_knn_mma<<<dim3(NB1 / 128, 4, 1), 256, KNN_SMEM>>>(pa, pb, sqn, pd, pi, NB1, 1);
    k_merge<<<dim3(NB1 / 128, 4), 128>>>(pd, pi, idx, NB1, 1);
    k_gather<<<dim3(NB1, 4), 192>>>(xn, idx, nb, NB1);
    k_lin<false><<<dim3(4 * NB1 / 64, 3), 256>>>(nb, xn, W1l, W1r, b1l, sg);
    k_wnorm<<<1, 192>>>(p1w, scal);
    k_scores<<<4 * NB1 / 8, 256>>>(sg, p1w, scal, sc);
    k_sort<<<4, 1024, NB1 * 8>>>(sc, perm, sv, NB1, NB2);
    k_gatherpool<<<dim3(NB2, 4), 192>>>(sg, perm, sv, pl, NB1, NB2);
    k_lin<true><<<dim3(4 * NB2 / 64, 3), 256>>>(pl, pl, ggam, ggam, gbeta, gd);

    // ---- stage 2 (N = 1024, kNN col-split 4-way) ----
    k_sqn<<<dim3(NB2, 4), 192>>>(gd, sqn, NB2);
    k_split2<<<dim3(NB2, 4), 192>>>(gd, pa, pb, NB2);
    k_knn_mma<<<dim3(NB2 / 128, 4, 4), 256, KNN_SMEM>>>(pa, pb, sqn, pd, pi, NB2, 4);
    k_merge<<<dim3(NB2 / 128, 4), 128>>>(pd, pi, idx, NB2, 4);
    k_gather<<<dim3(NB2, 4), 192>>>(gd, idx, nb, NB2);
    k_lin<false><<<dim3(4 * NB2 / 64, 3), 256>>>(nb, gd, W2l, W2r, b2l, sg2);
    k_wnorm<<<1, 192>>>(p2w, scal + 1);
    k_scores<<<4 * NB2 / 8, 256>>>(sg2, p2w, scal + 1, sc);
    k_sort<<<4, 1024, NB2 * 8>>>(sc, perm, sv, NB2, 256);
    k_gatherpool<<<dim3(256, 4), 192>>>(sg2, perm, sv, pl2, NB2, 256);
    k_final<<<dim3(256, 4), 192>>>(pl2, out);
}